// round 12
// baseline (speedup 1.0000x reference)
#include <cuda_runtime.h>
#include <cuda_bf16.h>

#define BB_ 64
#define LL_ 2048

typedef unsigned long long ull;
typedef unsigned int u32;

// Ping-pong buffers for the tree levels.
__device__ float g_bufA[BB_ * LL_ * 128];        // 67 MB
__device__ float g_bufB[BB_ * (LL_ / 2) * 128];  // 33.5 MB
// Permuted split W_hh: [chunk(4)][n(160)][k(128)] bf16, n = gate*32 + col
__device__ __align__(16) __nv_bfloat16 g_Whi[4 * 160 * 128];
__device__ __align__(16) __nv_bfloat16 g_Wlo[4 * 160 * 128];
// Split W_wh transposed: [n(128)][k(128)]
__device__ __align__(16) __nv_bfloat16 g_Ehi[128 * 128];
__device__ __align__(16) __nv_bfloat16 g_Elo[128 * 128];

extern __shared__ float smem[];

// ---------------- scalar helpers ----------------
__device__ __forceinline__ float tanhfast(float x) {
    float y; asm("tanh.approx.f32 %0, %1;" : "=f"(y) : "f"(x)); return y;
}
__device__ __forceinline__ float sig_fast(float x) {
    return fmaf(0.5f, tanhfast(0.5f * x), 0.5f);
}
__device__ __forceinline__ float tanh_f(float x) {
    return 1.0f - 2.0f / (__expf(2.0f * x) + 1.0f);
}

// ---------------- cp.async ----------------
__device__ __forceinline__ void cp16(void* s, const void* g) {
    unsigned a = (unsigned)__cvta_generic_to_shared(s);
    asm volatile("cp.async.cg.shared.global [%0], [%1], 16;" :: "r"(a), "l"(g));
}
#define CP_COMMIT() asm volatile("cp.async.commit_group;")
#define CP_WAIT0()  asm volatile("cp.async.wait_group 0;")

// ---------------- mma.sync helpers ----------------
__device__ __forceinline__ u32 smem_u32(const void* p) {
    u32 a;
    asm("{ .reg .u64 t; cvta.to.shared.u64 t, %1; cvt.u32.u64 %0, t; }" : "=r"(a) : "l"(p));
    return a;
}
__device__ __forceinline__ void ldsm4(u32* r, u32 saddr) {
    asm volatile("ldmatrix.sync.aligned.m8n8.x4.shared.b16 {%0,%1,%2,%3}, [%4];"
                 : "=r"(r[0]), "=r"(r[1]), "=r"(r[2]), "=r"(r[3]) : "r"(saddr));
}
__device__ __forceinline__ void ldsm2(u32* r, u32 saddr) {
    asm volatile("ldmatrix.sync.aligned.m8n8.x2.shared.b16 {%0,%1}, [%2];"
                 : "=r"(r[0]), "=r"(r[1]) : "r"(saddr));
}
__device__ __forceinline__ void mma16816(float* d, const u32* a, u32 b0, u32 b1) {
    asm volatile(
        "mma.sync.aligned.m16n8k16.row.col.f32.bf16.bf16.f32 "
        "{%0,%1,%2,%3}, {%4,%5,%6,%7}, {%8,%9}, {%0,%1,%2,%3};"
        : "+f"(d[0]), "+f"(d[1]), "+f"(d[2]), "+f"(d[3])
        : "r"(a[0]), "r"(a[1]), "r"(a[2]), "r"(a[3]), "r"(b0), "r"(b1));
}

// =====================================================================
// Prep (single launch): split W_hh and W_wh to bf16 hi/lo.
// =====================================================================
__global__ void prep_both(const float* __restrict__ Whh, const float* __restrict__ Wwh) {
    int idx = blockIdx.x * 256 + threadIdx.x;
    if (idx < 128 * 640) {
        int k = idx / 640, col = idx - k * 640;
        int g = col >> 7, c = col & 127;
        int chunk = c >> 5, cl = c & 31;
        int n = g * 32 + cl;
        float w = Whh[idx];
        __nv_bfloat16 hi = __float2bfloat16_rn(w);
        __nv_bfloat16 lo = __float2bfloat16_rn(w - __bfloat162float(hi));
        int dst = (chunk * 160 + n) * 128 + k;
        g_Whi[dst] = hi;
        g_Wlo[dst] = lo;
    } else if (idx < 128 * 640 + 128 * 128) {
        int e = idx - 128 * 640;
        int k = e >> 7, n = e & 127;
        float w = Wwh[e];
        __nv_bfloat16 hi = __float2bfloat16_rn(w);
        __nv_bfloat16 lo = __float2bfloat16_rn(w - __bfloat162float(hi));
        g_Ehi[n * 128 + k] = hi;
        g_Elo[n * 128 + k] = lo;
    }
}

// =====================================================================
// PERSISTENT embed, cp.async-pipelined gather. h0 = emb[ids] @ W_wh.
// Tile N+1's gather (cp.async -> f32 staging) overlaps tile N's MMA.
// smem: Ahi 16K | Alo 16K | Bhi 32K | Blo 32K... NO: B is hi+lo (3-split).
// Layout: Ahi 0 | Alo 16K | Bhi 32K | Blo 64K | AX(f32 stage) 96K... too big.
// => B hi 32K + lo 32K = 64K, A 32K, AX 32K -> 128K > 114. So embed keeps
// the 3-split with B resident 64K? That was round-10: A 32K + B 64K = 96K.
// Adding AX 32K -> 128K breaks 2 CTAs/SM. Instead stage AX IN PLACE of the
// Alo region during gather? No: need AX while converting into Ahi/Alo.
// Resolution: stage AX into the Blo region? B is read-only after fill...
// Simplest correct layout: AX overlaps nothing; shrink to 1.5 stage:
//   Ahi 16K | Alo 16K | Bhi 32K | Blo 32K | AX 32K = 128K -> 1 CTA/SM. Bad.
// Final choice: keep 2 CTAs/SM by staging HALF a tile (32 rows = 16K):
//   two half-tile stages per tile, each overlapped with the other's convert.
//   Ahi 16K | Alo 16K | Bhi 32K | Blo 32K | AX 16K = 112K -> 2 CTAs/SM.
// =====================================================================
#define EB_ALO 16384
#define EB_BHI 32768
#define EB_BLO 65536
#define EB_AX  98304
#define EB_SM  114688

__global__ __launch_bounds__(256, 2) void embed_pers(const int* __restrict__ ids,
                                                     const float* __restrict__ emb,
                                                     int ntiles) {
    char* sm = (char*)smem;
    int t = threadIdx.x;

    // B fill once via cp.async (hi + lo).
    for (int j = t; j < 2 * 128 * 16; j += 256) {
        int split = j >> 11, rem = j & 2047;
        int row = rem >> 4, q = rem & 15;
        const __nv_bfloat16* src = split ? g_Elo : g_Ehi;
        u32 kpb = (u32)(4 * q) ^ ((row & 7) << 2);
        cp16(sm + EB_BHI + split * 32768 + (row * 64 + kpb) * 4, &src[row * 128 + q * 8]);
    }
    CP_COMMIT();

    u32 smb = smem_u32(sm);
    int lane = t & 31, warp = t >> 5;
    int wm = warp >> 2, wn = warp & 3;
    int t8 = lane >> 3, l7 = lane & 7;
    u32 xsw = (u32)(l7 << 2);
    int arow = wm * 32 + (t8 & 1) * 8 + l7;
    u32 tka = (u32)((t8 >> 1) * 4);
    int brow = wn * 32 + (t8 >> 1) * 8 + l7;
    u32 tkb = (u32)((t8 & 1) * 4);
    int grp = lane >> 2, tid4 = lane & 3;

    // Stage half-tile h (32 rows) of tile 'tile' into AX via cp.async.
    // Each thread: 4 cp16s (rolled). i in [0,1024): rr=i>>5 (0..31), c4=i&31.
    auto stage_half = [&](int tile, int h) {
        int r0 = tile * 64 + h * 32;
        for (int i = t; i < 32 * 32; i += 256) {
            int rr = i >> 5, c4 = i & 31;
            int id = ids[r0 + rr];
            cp16(sm + EB_AX + i * 16, &((const float4*)emb)[(long long)id * 32 + c4]);
        }
        CP_COMMIT();
    };
    // Convert staged half-tile h: AX f32 -> Ahi/Alo bf16 swizzled.
    auto convert_half = [&](int h) {
        for (int i = t; i < 32 * 32; i += 256) {
            int rr = (i >> 5) + h * 32, c4 = i & 31;
            float4 v = *(const float4*)(sm + EB_AX + i * 16);
            float xv[4] = {v.x, v.y, v.z, v.w};
            __nv_bfloat16 hi[4], lo[4];
#pragma unroll
            for (int j = 0; j < 4; j++) {
                hi[j] = __float2bfloat16_rn(xv[j]);
                lo[j] = __float2bfloat16_rn(xv[j] - __bfloat162float(hi[j]));
            }
            u32 sw = (u32)(2 * c4) ^ ((rr & 7) << 2);
            *(uint2*)(sm + (rr * 64 + sw) * 4) = *(uint2*)hi;
            *(uint2*)(sm + EB_ALO + (rr * 64 + sw) * 4) = *(uint2*)lo;
        }
    };

    int tile0 = blockIdx.x;
    if (tile0 < ntiles) stage_half(tile0, 0);  // prologue (after B commit)

    for (int tile = tile0; tile < ntiles; tile += gridDim.x) {
        // half 0: wait, convert; stage half 1.
        CP_WAIT0();
        __syncthreads();            // AX(h0) ready; prev MMA done (Ahi/Alo free)
        convert_half(0);
        __syncthreads();            // AX free
        stage_half(tile, 1);
        CP_WAIT0();
        __syncthreads();            // AX(h1) ready
        convert_half(1);
        __syncthreads();            // Ahi/Alo complete, AX free
        // Overlap next tile's half-0 gather with this tile's MMA.
        int nxt = tile + gridDim.x;
        if (nxt < ntiles) stage_half(nxt, 0);

        int r0 = tile * 64;
        float acc[2][4][4];
#pragma unroll
        for (int a = 0; a < 2; a++)
#pragma unroll
            for (int b = 0; b < 4; b++)
#pragma unroll
                for (int c = 0; c < 4; c++) acc[a][b][c] = 0.0f;

#pragma unroll 1
        for (int ks = 0; ks < 8; ks++) {
#pragma unroll
            for (int split = 0; split < 3; split++) {
                u32 abase = smb + ((split == 2) ? (u32)EB_ALO : 0u);
                u32 bbase = smb + (u32)EB_BHI + ((split == 1) ? 32768u : 0u);
                u32 ka = (((u32)(ks * 8) + tka) ^ xsw) * 4;
                u32 kb = (((u32)(ks * 8) + tkb) ^ xsw) * 4;
                u32 af[2][4];
                ldsm4(af[0], abase + (u32)arow * 256 + ka);
                ldsm4(af[1], abase + (u32)(arow + 16) * 256 + ka);
#pragma unroll
                for (int np = 0; np < 2; np++) {
                    u32 bf[4];
                    ldsm4(bf, bbase + (u32)(brow + np * 16) * 256 + kb);
                    mma16816(acc[0][2 * np], af[0], bf[0], bf[1]);
                    mma16816(acc[0][2 * np + 1], af[0], bf[2], bf[3]);
                    mma16816(acc[1][2 * np], af[1], bf[0], bf[1]);
                    mma16816(acc[1][2 * np + 1], af[1], bf[2], bf[3]);
                }
            }
        }

#pragma unroll
        for (int mf = 0; mf < 2; mf++)
#pragma unroll
            for (int nf = 0; nf < 4; nf++) {
                int row = r0 + wm * 32 + mf * 16 + grp;
                int col = wn * 32 + nf * 8 + tid4 * 2;
                *(float2*)&g_bufA[(long long)row * 128 + col] =
                    make_float2(acc[mf][nf][0], acc[mf][nf][1]);
                *(float2*)&g_bufA[(long long)(row + 8) * 128 + col] =
                    make_float2(acc[mf][nf][2], acc[mf][nf][3]);
            }
    }
}

// =====================================================================
// Persistent tree-level kernel (BYTE-IDENTICAL to round-10 passing one).
// 2 CTAs/SM. Grid (<=74, 4 chunks). CTA = M=64 x N=160 (5 gates x 32).
// smem: A 2x16KB | B 2x40KB | bias 640B = 115328 B.
// =====================================================================
#define QB_ALO 16384
#define QB_B 32768
#define QB_BIAS 114688
#define QB_SM 115328

__global__ __launch_bounds__(256, 2) void combine_q(int src_sel,
                                                    float* __restrict__ out_param,
                                                    int dst_sel,
                                                    const float* __restrict__ bhh,
                                                    int lg_nhalf, int ntiles) {
    char* sm = (char*)smem;
    int t = threadIdx.x;
    int chunk = blockIdx.y;
    int n_half = 1 << lg_nhalf;

    const float* hin = (src_sel == 0) ? g_bufA : g_bufB;
    float* hout = (dst_sel == 0) ? g_bufA : (dst_sel == 1) ? g_bufB : out_param;

    // B fill once via cp.async: [split(2)][row 160][16 uint4], swizzled.
    for (int j = t; j < 2 * 160 * 16; j += 256) {
        int split = j / 2560, rem = j - split * 2560;
        int row = rem >> 4, q = rem & 15;
        const __nv_bfloat16* src = split ? g_Wlo : g_Whi;
        u32 kpb = (u32)(4 * q) ^ ((row & 7) << 2);
        cp16(sm + QB_B + split * 40960 + (row * 64 + kpb) * 4,
             &src[(chunk * 160 + row) * 128 + q * 8]);
    }
    CP_COMMIT();
    float* bias_s = (float*)(sm + QB_BIAS);
    for (int j = t; j < 160; j += 256)
        bias_s[j] = 2.0f * bhh[(j >> 5) * 128 + chunk * 32 + (j & 31)];

    u32 smb = smem_u32(sm);
    int lane = t & 31, warp = t >> 5;
    int wm = warp >> 2, wn = warp & 3;  // 2 x 4
    int t8 = lane >> 3, l7 = lane & 7;
    u32 xsw = (u32)(l7 << 2);
    int arow = wm * 32 + (t8 & 1) * 8 + l7;
    u32 tka = (u32)((t8 >> 1) * 4);
    int rowB = wn * 8 + l7;
    int bgsel = t8 >> 1;
    u32 tkb = (u32)((t8 & 1) * 4);
    int grp = lane >> 2, tid4 = lane & 3;
    int cl = wn * 8 + tid4 * 2;
    int hcol = chunk * 32 + cl;

    const float4* hin4 = (const float4*)hin;

    for (int tile = blockIdx.x; tile < ntiles; tile += gridDim.x) {
        int r0 = tile * 64;
        __syncthreads();  // previous tile's MMA done before A overwrite

        // A fill: x = hl + hr, rn split, swizzled (rolled loop).
        for (int i = t; i < 64 * 32; i += 256) {
            int rr = i >> 5, c4 = i & 31;
            int r = r0 + rr;
            int b = r >> lg_nhalf;
            int iw = r - (b << lg_nhalf);
            long long base = (long long)b * (2 * n_half);
            float4 l4 = hin4[(base + 2 * iw) * 32 + c4];
            float4 r4 = hin4[(base + 2 * iw + 1) * 32 + c4];
            float xv[4] = {l4.x + r4.x, l4.y + r4.y, l4.z + r4.z, l4.w + r4.w};
            __nv_bfloat16 hi[4], lo[4];
#pragma unroll
            for (int j = 0; j < 4; j++) {
                hi[j] = __float2bfloat16_rn(xv[j]);
                lo[j] = __float2bfloat16_rn(xv[j] - __bfloat162float(hi[j]));
            }
            u32 sw = (u32)(2 * c4) ^ ((rr & 7) << 2);
            *(uint2*)(sm + (rr * 64 + sw) * 4) = *(uint2*)hi;
            *(uint2*)(sm + QB_ALO + (rr * 64 + sw) * 4) = *(uint2*)lo;
        }

        // Prefetch epilogue operands (latency drains behind the MMA loop).
        float2 hl_pre[2][2], hr_pre[2][2];
#pragma unroll
        for (int mf = 0; mf < 2; mf++)
#pragma unroll
            for (int half = 0; half < 2; half++) {
                int rr = wm * 32 + mf * 16 + grp + half * 8;
                int r = r0 + rr;
                int b = r >> lg_nhalf;
                int iw = r - (b << lg_nhalf);
                long long rowL = (long long)b * (2 * n_half) + 2 * iw;
                hl_pre[mf][half] = *(const float2*)&hin[rowL * 128 + hcol];
                hr_pre[mf][half] = *(const float2*)&hin[(rowL + 1) * 128 + hcol];
            }

        CP_WAIT0();  // B ready (no-op after first tile)
        __syncthreads();

        float acc[2][5][4];
#pragma unroll
        for (int a = 0; a < 2; a++)
#pragma unroll
            for (int g = 0; g < 5; g++)
#pragma unroll
                for (int c = 0; c < 4; c++) acc[a][g][c] = 0.0f;

#pragma unroll 1
        for (int ks = 0; ks < 8; ks++) {
#pragma unroll
            for (int split = 0; split < 3; split++) {
                u32 abase = smb + ((split == 2) ? (u32)QB_ALO : 0u);
                u32 bbase = smb + QB_B + ((split == 1) ? 40960u : 0u);
                u32 ka = (((u32)(ks * 8) + tka) ^ xsw) * 4;
                u32 kb = (((u32)(ks * 8) + tkb) ^ xsw) * 4;
                u32 af[2][4];
                ldsm4(af[0], abase + (u32)arow * 256 + ka);
                ldsm4(af[1], abase + (u32)(arow + 16) * 256 + ka);
                u32 b01[4], b23[4], b4[2];
                ldsm4(b01, bbase + (u32)((0 + bgsel) * 32 + rowB) * 256 + kb);
                ldsm4(b23, bbase + (u32)((2 + bgsel) * 32 + rowB) * 256 + kb);
                ldsm2(b4, bbase + (u32)(4 * 32 + rowB) * 256 + kb);
                mma16816(acc[0][0], af[0], b01[0], b01[1]);
                mma16816(acc[1][0], af[1], b01[0], b01[1]);
                mma16816(acc[0][1], af[0], b01[2], b01[3]);
                mma16816(acc[1][1], af[1], b01[2], b01[3]);
                mma16816(acc[0][2], af[0], b23[0], b23[1]);
                mma16816(acc[1][2], af[1], b23[0], b23[1]);
                mma16816(acc[0][3], af[0], b23[2], b23[3]);
                mma16816(acc[1][3], af[1], b23[2], b23[3]);
                mma16816(acc[0][4], af[0], b4[0], b4[1]);
                mma16816(acc[1][4], af[1], b4[0], b4[1]);
            }
        }

        // Epilogue: gates + hl/hr already in registers.
#pragma unroll
        for (int mf = 0; mf < 2; mf++) {
#pragma unroll
            for (int half = 0; half < 2; half++) {
                int rr = wm * 32 + mf * 16 + grp + half * 8;
                int r = r0 + rr;
                float hl2[2] = {hl_pre[mf][half].x, hl_pre[mf][half].y};
                float hr2[2] = {hr_pre[mf][half].x, hr_pre[mf][half].y};
                float ov[2];
#pragma unroll
                for (int j = 0; j < 2; j++) {
                    int e = half * 2 + j;
                    float si = acc[mf][0][e] + bias_s[0 * 32 + cl + j];
                    float sl = acc[mf][1][e] + bias_s[1 * 32 + cl + j];
                    float sr = acc[mf][2][e] + bias_s[2 * 32 + cl + j];
                    float so = acc[mf][3][e] + bias_s[3 * 32 + cl + j];
                    float sg = acc[mf][4][e] + bias_s[4 * 32 + cl + j];
                    float cc = sig_fast(si) * tanh_f(sg) + sig_fast(sl) * hl2[j] +
                               sig_fast(sr) * hr2[j];
                    ov[j] = sig_fast(so) * tanh_f(cc);
                }
                *(float2*)&hout[(long long)r * 128 + hcol] = make_float2(ov[0], ov[1]);
            }
        }
    }
}

// ---------------- launcher ----------------
extern "C" void kernel_launch(void* const* d_in, const int* in_sizes, int n_in,
                              void* d_out, int out_size) {
    const int* ids = (const int*)d_in[0];
    const float* emb = (const float*)d_in[1];
    const float* Wwh = (const float*)d_in[2];
    const float* Whh = (const float*)d_in[3];
    const float* bhh = (const float*)d_in[4];
    float* out = (float*)d_out;

    cudaFuncSetAttribute(embed_pers, cudaFuncAttributeMaxDynamicSharedMemorySize, EB_SM);
    cudaFuncSetAttribute(combine_q, cudaFuncAttributeMaxDynamicSharedMemorySize, QB_SM);

    prep_both<<<(128 * 640 + 128 * 128 + 255) / 256, 256>>>(Whh, Wwh);

    {
        int ntiles = (BB_ * LL_) / 64;  // 2048
        int gx = ntiles < 296 ? ntiles : 296;
        embed_pers<<<gx, 256, EB_SM>>>(ids, emb, ntiles);
    }

    for (int tlev = 1; tlev <= 11; ++tlev) {
        int ntiles = (BB_ * (LL_ >> tlev)) / 64;  // M=64 tiles
        int lg = 11 - tlev;
        int src_sel = (tlev & 1) ? 0 : 1;
        int dst_sel = (tlev == 11) ? 2 : ((tlev & 1) ? 1 : 0);
        int gx = ntiles < 74 ? ntiles : 74;
        dim3 grid(gx, 4);
        combine_q<<<grid, 256, QB_SM>>>(src_sel, out, dst_sel, bhh, lg, ntiles);
    }
}

// round 13
// speedup vs baseline: 1.0594x; 1.0594x over previous
#include <cuda_runtime.h>
#include <cuda_bf16.h>

#define BB_ 64
#define LL_ 2048
#define GX_ 74
#define GCTAS_ (GX_ * 4)

typedef unsigned long long ull;
typedef unsigned int u32;

// Ping-pong buffers for the tree levels.
__device__ float g_bufA[BB_ * LL_ * 128];        // 67 MB
__device__ float g_bufB[BB_ * (LL_ / 2) * 128];  // 33.5 MB
// Permuted split W_hh: [chunk(4)][n(160)][k(128)] bf16, n = gate*32 + col
__device__ __align__(16) __nv_bfloat16 g_Whi[4 * 160 * 128];
__device__ __align__(16) __nv_bfloat16 g_Wlo[4 * 160 * 128];
// Split W_wh transposed: [n(128)][k(128)]
__device__ __align__(16) __nv_bfloat16 g_Ehi[128 * 128];
__device__ __align__(16) __nv_bfloat16 g_Elo[128 * 128];
// Device-wide barrier counter (reset by prep_both every replay).
__device__ unsigned g_bar;

extern __shared__ float smem[];

// ---------------- scalar helpers ----------------
__device__ __forceinline__ float tanhfast(float x) {
    float y; asm("tanh.approx.f32 %0, %1;" : "=f"(y) : "f"(x)); return y;
}
__device__ __forceinline__ float sig_fast(float x) {
    return fmaf(0.5f, tanhfast(0.5f * x), 0.5f);
}
__device__ __forceinline__ float tanh_f(float x) {
    return 1.0f - 2.0f / (__expf(2.0f * x) + 1.0f);
}

// ---------------- cp.async ----------------
__device__ __forceinline__ void cp16(void* s, const void* g) {
    unsigned a = (unsigned)__cvta_generic_to_shared(s);
    asm volatile("cp.async.cg.shared.global [%0], [%1], 16;" :: "r"(a), "l"(g));
}
#define CP_COMMIT() asm volatile("cp.async.commit_group;")
#define CP_WAIT0()  asm volatile("cp.async.wait_group 0;")

// ---------------- mma.sync helpers ----------------
__device__ __forceinline__ u32 smem_u32(const void* p) {
    u32 a;
    asm("{ .reg .u64 t; cvta.to.shared.u64 t, %1; cvt.u32.u64 %0, t; }" : "=r"(a) : "l"(p));
    return a;
}
__device__ __forceinline__ void ldsm4(u32* r, u32 saddr) {
    asm volatile("ldmatrix.sync.aligned.m8n8.x4.shared.b16 {%0,%1,%2,%3}, [%4];"
                 : "=r"(r[0]), "=r"(r[1]), "=r"(r[2]), "=r"(r[3]) : "r"(saddr));
}
__device__ __forceinline__ void ldsm2(u32* r, u32 saddr) {
    asm volatile("ldmatrix.sync.aligned.m8n8.x2.shared.b16 {%0,%1}, [%2];"
                 : "=r"(r[0]), "=r"(r[1]) : "r"(saddr));
}
__device__ __forceinline__ void mma16816(float* d, const u32* a, u32 b0, u32 b1) {
    asm volatile(
        "mma.sync.aligned.m16n8k16.row.col.f32.bf16.bf16.f32 "
        "{%0,%1,%2,%3}, {%4,%5,%6,%7}, {%8,%9}, {%0,%1,%2,%3};"
        : "+f"(d[0]), "+f"(d[1]), "+f"(d[2]), "+f"(d[3])
        : "r"(a[0]), "r"(a[1]), "r"(a[2]), "r"(a[3]), "r"(b0), "r"(b1));
}

// =====================================================================
// Prep (single launch): split weights to bf16 hi/lo; reset barrier.
// =====================================================================
__global__ void prep_both(const float* __restrict__ Whh, const float* __restrict__ Wwh) {
    int idx = blockIdx.x * 256 + threadIdx.x;
    if (idx == 0) g_bar = 0u;
    if (idx < 128 * 640) {
        int k = idx / 640, col = idx - k * 640;
        int g = col >> 7, c = col & 127;
        int chunk = c >> 5, cl = c & 31;
        int n = g * 32 + cl;
        float w = Whh[idx];
        __nv_bfloat16 hi = __float2bfloat16_rn(w);
        __nv_bfloat16 lo = __float2bfloat16_rn(w - __bfloat162float(hi));
        int dst = (chunk * 160 + n) * 128 + k;
        g_Whi[dst] = hi;
        g_Wlo[dst] = lo;
    } else if (idx < 128 * 640 + 128 * 128) {
        int e = idx - 128 * 640;
        int k = e >> 7, n = e & 127;
        float w = Wwh[e];
        __nv_bfloat16 hi = __float2bfloat16_rn(w);
        __nv_bfloat16 lo = __float2bfloat16_rn(w - __bfloat162float(hi));
        g_Ehi[n * 128 + k] = hi;
        g_Elo[n * 128 + k] = lo;
    }
}

// =====================================================================
// PERSISTENT embed (round-10 version): h0 = emb[ids] @ W_wh.
// smem: Ahi 16K | Alo 16K | Bhi 32K | Blo 32K = 96KB -> 2 CTAs/SM.
// =====================================================================
__global__ __launch_bounds__(256, 2) void embed_pers(const int* __restrict__ ids,
                                                     const float* __restrict__ emb,
                                                     int ntiles) {
    char* sm = (char*)smem;
    int t = threadIdx.x;

    for (int j = t; j < 2 * 128 * 16; j += 256) {
        int split = j >> 11, rem = j & 2047;
        int row = rem >> 4, q = rem & 15;
        const __nv_bfloat16* src = split ? g_Elo : g_Ehi;
        u32 kpb = (u32)(4 * q) ^ ((row & 7) << 2);
        cp16(sm + 32768 + split * 32768 + (row * 64 + kpb) * 4, &src[row * 128 + q * 8]);
    }
    CP_COMMIT();

    u32 smb = smem_u32(sm);
    int lane = t & 31, warp = t >> 5;
    int wm = warp >> 2, wn = warp & 3;
    int t8 = lane >> 3, l7 = lane & 7;
    u32 xsw = (u32)(l7 << 2);
    int arow = wm * 32 + (t8 & 1) * 8 + l7;
    u32 tka = (u32)((t8 >> 1) * 4);
    int brow = wn * 32 + (t8 >> 1) * 8 + l7;
    u32 tkb = (u32)((t8 & 1) * 4);
    int grp = lane >> 2, tid4 = lane & 3;

    for (int tile = blockIdx.x; tile < ntiles; tile += gridDim.x) {
        int r0 = tile * 64;
        __syncthreads();

        for (int i = t; i < 64 * 32; i += 256) {
            int rr = i >> 5, c4 = i & 31;
            int id = ids[r0 + rr];
            float4 v = ((const float4*)emb)[(long long)id * 32 + c4];
            float xv[4] = {v.x, v.y, v.z, v.w};
            __nv_bfloat16 hi[4], lo[4];
#pragma unroll
            for (int j = 0; j < 4; j++) {
                hi[j] = __float2bfloat16_rn(xv[j]);
                lo[j] = __float2bfloat16_rn(xv[j] - __bfloat162float(hi[j]));
            }
            u32 sw = (u32)(2 * c4) ^ ((rr & 7) << 2);
            *(uint2*)(sm + (rr * 64 + sw) * 4) = *(uint2*)hi;
            *(uint2*)(sm + 16384 + (rr * 64 + sw) * 4) = *(uint2*)lo;
        }
        CP_WAIT0();
        __syncthreads();

        float acc[2][4][4];
#pragma unroll
        for (int a = 0; a < 2; a++)
#pragma unroll
            for (int b = 0; b < 4; b++)
#pragma unroll
                for (int c = 0; c < 4; c++) acc[a][b][c] = 0.0f;

#pragma unroll 1
        for (int ks = 0; ks < 8; ks++) {
#pragma unroll
            for (int split = 0; split < 3; split++) {
                u32 abase = smb + ((split == 2) ? 16384u : 0u);
                u32 bbase = smb + 32768u + ((split == 1) ? 32768u : 0u);
                u32 ka = (((u32)(ks * 8) + tka) ^ xsw) * 4;
                u32 kb = (((u32)(ks * 8) + tkb) ^ xsw) * 4;
                u32 af[2][4];
                ldsm4(af[0], abase + (u32)arow * 256 + ka);
                ldsm4(af[1], abase + (u32)(arow + 16) * 256 + ka);
#pragma unroll
                for (int np = 0; np < 2; np++) {
                    u32 bf[4];
                    ldsm4(bf, bbase + (u32)(brow + np * 16) * 256 + kb);
                    mma16816(acc[0][2 * np], af[0], bf[0], bf[1]);
                    mma16816(acc[0][2 * np + 1], af[0], bf[2], bf[3]);
                    mma16816(acc[1][2 * np], af[1], bf[0], bf[1]);
                    mma16816(acc[1][2 * np + 1], af[1], bf[2], bf[3]);
                }
            }
        }

#pragma unroll
        for (int mf = 0; mf < 2; mf++)
#pragma unroll
            for (int nf = 0; nf < 4; nf++) {
                int row = r0 + wm * 32 + mf * 16 + grp;
                int col = wn * 32 + nf * 8 + tid4 * 2;
                *(float2*)&g_bufA[(long long)row * 128 + col] =
                    make_float2(acc[mf][nf][0], acc[mf][nf][1]);
                *(float2*)&g_bufA[(long long)(row + 8) * 128 + col] =
                    make_float2(acc[mf][nf][2], acc[mf][nf][3]);
            }
    }
}

// =====================================================================
// FUSED tree kernel: all 11 levels in one launch. Grid fixed (74,4) =
// 296 CTAs = exactly 2/SM x 148 -> co-resident; device-wide barrier
// between levels. B + bias loaded ONCE for the whole tree.
// smem: A 2x16KB | B 2x40KB | bias 640B = 115328 B -> 2 CTAs/SM.
// =====================================================================
#define QB_ALO 16384
#define QB_B 32768
#define QB_BIAS 114688
#define QB_SM 115328

__global__ __launch_bounds__(256, 2) void combine_all(float* __restrict__ out_param,
                                                      const float* __restrict__ bhh) {
    char* sm = (char*)smem;
    int t = threadIdx.x;
    int chunk = blockIdx.y;
    int bx = blockIdx.x;

    // B fill once: [split(2)][row 160][16 uint4], swizzled.
    for (int j = t; j < 2 * 160 * 16; j += 256) {
        int split = j / 2560, rem = j - split * 2560;
        int row = rem >> 4, q = rem & 15;
        const __nv_bfloat16* src = split ? g_Wlo : g_Whi;
        u32 kpb = (u32)(4 * q) ^ ((row & 7) << 2);
        cp16(sm + QB_B + split * 40960 + (row * 64 + kpb) * 4,
             &src[(chunk * 160 + row) * 128 + q * 8]);
    }
    CP_COMMIT();
    float* bias_s = (float*)(sm + QB_BIAS);
    for (int j = t; j < 160; j += 256)
        bias_s[j] = 2.0f * bhh[(j >> 5) * 128 + chunk * 32 + (j & 31)];
    CP_WAIT0();
    __syncthreads();  // B + bias ready for all levels

    u32 smb = smem_u32(sm);
    int lane = t & 31, warp = t >> 5;
    int wm = warp >> 2, wn = warp & 3;  // 2 x 4
    int t8 = lane >> 3, l7 = lane & 7;
    u32 xsw = (u32)(l7 << 2);
    int arow = wm * 32 + (t8 & 1) * 8 + l7;
    u32 tka = (u32)((t8 >> 1) * 4);
    int rowB = wn * 8 + l7;
    int bgsel = t8 >> 1;
    u32 tkb = (u32)((t8 & 1) * 4);
    int grp = lane >> 2, tid4 = lane & 3;
    int cl = wn * 8 + tid4 * 2;
    int hcol = chunk * 32 + cl;

    for (int lev = 1; lev <= 11; lev++) {
        int lg_nhalf = 11 - lev;
        int n_half = 1 << lg_nhalf;
        int ntiles = 2048 >> lev;  // M=64 tiles this level
        const float* hin = (lev & 1) ? g_bufA : g_bufB;
        float* hout = (lev == 11) ? out_param : ((lev & 1) ? g_bufB : g_bufA);
        const float4* hin4 = (const float4*)hin;

        for (int tile = bx; tile < ntiles; tile += GX_) {
            int r0 = tile * 64;
            __syncthreads();  // previous tile's MMA done before A overwrite

            // A fill: x = hl + hr, rn split, swizzled (rolled loop).
            for (int i = t; i < 64 * 32; i += 256) {
                int rr = i >> 5, c4 = i & 31;
                int r = r0 + rr;
                int b = r >> lg_nhalf;
                int iw = r - (b << lg_nhalf);
                long long base = (long long)b * (2 * n_half);
                float4 l4 = hin4[(base + 2 * iw) * 32 + c4];
                float4 r4 = hin4[(base + 2 * iw + 1) * 32 + c4];
                float xv[4] = {l4.x + r4.x, l4.y + r4.y, l4.z + r4.z, l4.w + r4.w};
                __nv_bfloat16 hi[4], lo[4];
#pragma unroll
                for (int j = 0; j < 4; j++) {
                    hi[j] = __float2bfloat16_rn(xv[j]);
                    lo[j] = __float2bfloat16_rn(xv[j] - __bfloat162float(hi[j]));
                }
                u32 sw = (u32)(2 * c4) ^ ((rr & 7) << 2);
                *(uint2*)(sm + (rr * 64 + sw) * 4) = *(uint2*)hi;
                *(uint2*)(sm + QB_ALO + (rr * 64 + sw) * 4) = *(uint2*)lo;
            }

            // Prefetch epilogue operands.
            float2 hl_pre[2][2], hr_pre[2][2];
#pragma unroll
            for (int mf = 0; mf < 2; mf++)
#pragma unroll
                for (int half = 0; half < 2; half++) {
                    int rr = wm * 32 + mf * 16 + grp + half * 8;
                    int r = r0 + rr;
                    int b = r >> lg_nhalf;
                    int iw = r - (b << lg_nhalf);
                    long long rowL = (long long)b * (2 * n_half) + 2 * iw;
                    hl_pre[mf][half] = *(const float2*)&hin[rowL * 128 + hcol];
                    hr_pre[mf][half] = *(const float2*)&hin[(rowL + 1) * 128 + hcol];
                }
            __syncthreads();

            float acc[2][5][4];
#pragma unroll
            for (int a = 0; a < 2; a++)
#pragma unroll
                for (int g = 0; g < 5; g++)
#pragma unroll
                    for (int c = 0; c < 4; c++) acc[a][g][c] = 0.0f;

#pragma unroll 1
            for (int ks = 0; ks < 8; ks++) {
#pragma unroll
                for (int split = 0; split < 3; split++) {
                    u32 abase = smb + ((split == 2) ? (u32)QB_ALO : 0u);
                    u32 bbase = smb + QB_B + ((split == 1) ? 40960u : 0u);
                    u32 ka = (((u32)(ks * 8) + tka) ^ xsw) * 4;
                    u32 kb = (((u32)(ks * 8) + tkb) ^ xsw) * 4;
                    u32 af[2][4];
                    ldsm4(af[0], abase + (u32)arow * 256 + ka);
                    ldsm4(af[1], abase + (u32)(arow + 16) * 256 + ka);
                    u32 b01[4], b23[4], b4[2];
                    ldsm4(b01, bbase + (u32)((0 + bgsel) * 32 + rowB) * 256 + kb);
                    ldsm4(b23, bbase + (u32)((2 + bgsel) * 32 + rowB) * 256 + kb);
                    ldsm2(b4, bbase + (u32)(4 * 32 + rowB) * 256 + kb);
                    mma16816(acc[0][0], af[0], b01[0], b01[1]);
                    mma16816(acc[1][0], af[1], b01[0], b01[1]);
                    mma16816(acc[0][1], af[0], b01[2], b01[3]);
                    mma16816(acc[1][1], af[1], b01[2], b01[3]);
                    mma16816(acc[0][2], af[0], b23[0], b23[1]);
                    mma16816(acc[1][2], af[1], b23[0], b23[1]);
                    mma16816(acc[0][3], af[0], b23[2], b23[3]);
                    mma16816(acc[1][3], af[1], b23[2], b23[3]);
                    mma16816(acc[0][4], af[0], b4[0], b4[1]);
                    mma16816(acc[1][4], af[1], b4[0], b4[1]);
                }
            }

            // Epilogue.
#pragma unroll
            for (int mf = 0; mf < 2; mf++) {
#pragma unroll
                for (int half = 0; half < 2; half++) {
                    int rr = wm * 32 + mf * 16 + grp + half * 8;
                    int r = r0 + rr;
                    float hl2[2] = {hl_pre[mf][half].x, hl_pre[mf][half].y};
                    float hr2[2] = {hr_pre[mf][half].x, hr_pre[mf][half].y};
                    float ov[2];
#pragma unroll
                    for (int j = 0; j < 2; j++) {
                        int e = half * 2 + j;
                        float si = acc[mf][0][e] + bias_s[0 * 32 + cl + j];
                        float sl = acc[mf][1][e] + bias_s[1 * 32 + cl + j];
                        float sr = acc[mf][2][e] + bias_s[2 * 32 + cl + j];
                        float so = acc[mf][3][e] + bias_s[3 * 32 + cl + j];
                        float sg = acc[mf][4][e] + bias_s[4 * 32 + cl + j];
                        float cc = sig_fast(si) * tanh_f(sg) + sig_fast(sl) * hl2[j] +
                                   sig_fast(sr) * hr2[j];
                        ov[j] = sig_fast(so) * tanh_f(cc);
                    }
                    *(float2*)&hout[(long long)r * 128 + hcol] = make_float2(ov[0], ov[1]);
                }
            }
        }

        // ---- device-wide barrier between levels ----
        if (lev < 11) {
            __threadfence();   // release: this CTA's hout stores visible
            __syncthreads();
            if (t == 0) {
                atomicAdd(&g_bar, 1u);
                unsigned target = (unsigned)(GCTAS_ * lev);
                while (atomicAdd(&g_bar, 0u) < target) __nanosleep(64);
            }
            __syncthreads();
            __threadfence();   // acquire: CCTL.IVALL flushes stale L1 lines
        }
    }
}

// ---------------- launcher ----------------
extern "C" void kernel_launch(void* const* d_in, const int* in_sizes, int n_in,
                              void* d_out, int out_size) {
    const int* ids = (const int*)d_in[0];
    const float* emb = (const float*)d_in[1];
    const float* Wwh = (const float*)d_in[2];
    const float* Whh = (const float*)d_in[3];
    const float* bhh = (const float*)d_in[4];
    float* out = (float*)d_out;

    const int smem_embed = 98304;
    cudaFuncSetAttribute(embed_pers, cudaFuncAttributeMaxDynamicSharedMemorySize, smem_embed);
    cudaFuncSetAttribute(combine_all, cudaFuncAttributeMaxDynamicSharedMemorySize, QB_SM);

    prep_both<<<(128 * 640 + 128 * 128 + 255) / 256, 256>>>(Whh, Wwh);

    {
        int ntiles = (BB_ * LL_) / 64;  // 2048
        int gx = ntiles < 296 ? ntiles : 296;
        embed_pers<<<gx, 256, smem_embed>>>(ids, emb, ntiles);
    }

    combine_all<<<dim3(GX_, 4), 256, QB_SM>>>(out, bhh);
}

// round 14
// speedup vs baseline: 1.0626x; 1.0030x over previous
#include <cuda_runtime.h>
#include <cuda_bf16.h>

#define BB_ 64
#define LL_ 2048
#define GX_ 74
#define GCTAS_ (GX_ * 4)

typedef unsigned long long ull;
typedef unsigned int u32;

// Ping-pong buffers for the tree levels.
__device__ float g_bufA[BB_ * LL_ * 128];        // 67 MB
__device__ float g_bufB[BB_ * (LL_ / 2) * 128];  // 33.5 MB
// Permuted split W_hh: [chunk(4)][n(160)][k(128)] bf16, n = gate*32 + col
__device__ __align__(16) __nv_bfloat16 g_Whi[4 * 160 * 128];
__device__ __align__(16) __nv_bfloat16 g_Wlo[4 * 160 * 128];
// Split W_wh transposed: [n(128)][k(128)]
__device__ __align__(16) __nv_bfloat16 g_Ehi[128 * 128];
__device__ __align__(16) __nv_bfloat16 g_Elo[128 * 128];
// Device-wide barrier counter (reset by prep_both every replay).
__device__ unsigned g_bar;

extern __shared__ float smem[];

// ---------------- scalar helpers ----------------
__device__ __forceinline__ float tanhfast(float x) {
    float y; asm("tanh.approx.f32 %0, %1;" : "=f"(y) : "f"(x)); return y;
}
__device__ __forceinline__ float sig_fast(float x) {
    return fmaf(0.5f, tanhfast(0.5f * x), 0.5f);
}
__device__ __forceinline__ float tanh_f(float x) {
    return 1.0f - 2.0f / (__expf(2.0f * x) + 1.0f);
}

// ---------------- cp.async ----------------
__device__ __forceinline__ void cp16(void* s, const void* g) {
    unsigned a = (unsigned)__cvta_generic_to_shared(s);
    asm volatile("cp.async.cg.shared.global [%0], [%1], 16;" :: "r"(a), "l"(g));
}
#define CP_COMMIT() asm volatile("cp.async.commit_group;")
#define CP_WAIT0()  asm volatile("cp.async.wait_group 0;")

// ---------------- mma.sync helpers ----------------
__device__ __forceinline__ u32 smem_u32(const void* p) {
    u32 a;
    asm("{ .reg .u64 t; cvta.to.shared.u64 t, %1; cvt.u32.u64 %0, t; }" : "=r"(a) : "l"(p));
    return a;
}
__device__ __forceinline__ void ldsm4(u32* r, u32 saddr) {
    asm volatile("ldmatrix.sync.aligned.m8n8.x4.shared.b16 {%0,%1,%2,%3}, [%4];"
                 : "=r"(r[0]), "=r"(r[1]), "=r"(r[2]), "=r"(r[3]) : "r"(saddr));
}
__device__ __forceinline__ void ldsm2(u32* r, u32 saddr) {
    asm volatile("ldmatrix.sync.aligned.m8n8.x2.shared.b16 {%0,%1}, [%2];"
                 : "=r"(r[0]), "=r"(r[1]) : "r"(saddr));
}
__device__ __forceinline__ void mma16816(float* d, const u32* a, u32 b0, u32 b1) {
    asm volatile(
        "mma.sync.aligned.m16n8k16.row.col.f32.bf16.bf16.f32 "
        "{%0,%1,%2,%3}, {%4,%5,%6,%7}, {%8,%9}, {%0,%1,%2,%3};"
        : "+f"(d[0]), "+f"(d[1]), "+f"(d[2]), "+f"(d[3])
        : "r"(a[0]), "r"(a[1]), "r"(a[2]), "r"(a[3]), "r"(b0), "r"(b1));
}

// =====================================================================
// Prep (single launch): split weights to bf16 hi/lo; reset barrier.
// =====================================================================
__global__ void prep_both(const float* __restrict__ Whh, const float* __restrict__ Wwh) {
    int idx = blockIdx.x * 256 + threadIdx.x;
    if (idx == 0) g_bar = 0u;
    if (idx < 128 * 640) {
        int k = idx / 640, col = idx - k * 640;
        int g = col >> 7, c = col & 127;
        int chunk = c >> 5, cl = c & 31;
        int n = g * 32 + cl;
        float w = Whh[idx];
        __nv_bfloat16 hi = __float2bfloat16_rn(w);
        __nv_bfloat16 lo = __float2bfloat16_rn(w - __bfloat162float(hi));
        int dst = (chunk * 160 + n) * 128 + k;
        g_Whi[dst] = hi;
        g_Wlo[dst] = lo;
    } else if (idx < 128 * 640 + 128 * 128) {
        int e = idx - 128 * 640;
        int k = e >> 7, n = e & 127;
        float w = Wwh[e];
        __nv_bfloat16 hi = __float2bfloat16_rn(w);
        __nv_bfloat16 lo = __float2bfloat16_rn(w - __bfloat162float(hi));
        g_Ehi[n * 128 + k] = hi;
        g_Elo[n * 128 + k] = lo;
    }
}

// =====================================================================
// MEGA-KERNEL: embed (level 0) + all 11 tree levels in ONE launch.
// Grid fixed (74,4) = 296 CTAs = exactly 2/SM x 148 -> co-resident.
// Grid-wide barrier between phases; B region reused (E-split 64K for
// embed, then W-split 80K for the tree).
// smem: A 2x16KB | B 2x40KB | bias 640B = 115328 B -> 2 CTAs/SM.
// =====================================================================
#define QB_ALO 16384
#define QB_B 32768
#define QB_BIAS 114688
#define QB_SM 115328

__device__ __forceinline__ void grid_bar(int t, unsigned target) {
    __threadfence();   // release
    __syncthreads();
    if (t == 0) {
        atomicAdd(&g_bar, 1u);
        while (atomicAdd(&g_bar, 0u) < target) __nanosleep(64);
    }
    __syncthreads();
    __threadfence();   // acquire (CCTL.IVALL flushes stale L1 lines)
}

__global__ __launch_bounds__(256, 2) void fused_all(const int* __restrict__ ids,
                                                    const float* __restrict__ emb,
                                                    float* __restrict__ out_param,
                                                    const float* __restrict__ bhh) {
    char* sm = (char*)smem;
    int t = threadIdx.x;
    int chunk = blockIdx.y;
    int bx = blockIdx.x;
    int flat = chunk * GX_ + bx;

    u32 smb = smem_u32(sm);
    int lane = t & 31, warp = t >> 5;
    int wm = warp >> 2, wn = warp & 3;  // 2 x 4
    int t8 = lane >> 3, l7 = lane & 7;
    u32 xsw = (u32)(l7 << 2);
    int arow = wm * 32 + (t8 & 1) * 8 + l7;
    u32 tka = (u32)((t8 >> 1) * 4);
    u32 tkb = (u32)((t8 & 1) * 4);
    int grp = lane >> 2, tid4 = lane & 3;
    // embed B mapping (N=128 across 4 warps)
    int brow_e = wn * 32 + (t8 >> 1) * 8 + l7;
    // tree B mapping (gate-aligned)
    int rowB = wn * 8 + l7;
    int bgsel = t8 >> 1;
    int cl = wn * 8 + tid4 * 2;
    int hcol = chunk * 32 + cl;

    // ================= PHASE 0: embed =================
    // B_e fill: E-split into QB_B (hi) / QB_B+32768 (lo).
    for (int j = t; j < 2 * 128 * 16; j += 256) {
        int split = j >> 11, rem = j & 2047;
        int row = rem >> 4, q = rem & 15;
        const __nv_bfloat16* src = split ? g_Elo : g_Ehi;
        u32 kpb = (u32)(4 * q) ^ ((row & 7) << 2);
        cp16(sm + QB_B + split * 32768 + (row * 64 + kpb) * 4, &src[row * 128 + q * 8]);
    }
    CP_COMMIT();

    for (int tile = flat; tile < 2048; tile += GCTAS_) {
        int r0 = tile * 64;
        __syncthreads();

        for (int i = t; i < 64 * 32; i += 256) {
            int rr = i >> 5, c4 = i & 31;
            int id = ids[r0 + rr];
            float4 v = ((const float4*)emb)[(long long)id * 32 + c4];
            float xv[4] = {v.x, v.y, v.z, v.w};
            __nv_bfloat16 hi[4], lo[4];
#pragma unroll
            for (int j = 0; j < 4; j++) {
                hi[j] = __float2bfloat16_rn(xv[j]);
                lo[j] = __float2bfloat16_rn(xv[j] - __bfloat162float(hi[j]));
            }
            u32 sw = (u32)(2 * c4) ^ ((rr & 7) << 2);
            *(uint2*)(sm + (rr * 64 + sw) * 4) = *(uint2*)hi;
            *(uint2*)(sm + QB_ALO + (rr * 64 + sw) * 4) = *(uint2*)lo;
        }
        CP_WAIT0();
        __syncthreads();

        float acc[2][4][4];
#pragma unroll
        for (int a = 0; a < 2; a++)
#pragma unroll
            for (int b = 0; b < 4; b++)
#pragma unroll
                for (int c = 0; c < 4; c++) acc[a][b][c] = 0.0f;

#pragma unroll 1
        for (int ks = 0; ks < 8; ks++) {
#pragma unroll
            for (int split = 0; split < 3; split++) {
                u32 abase = smb + ((split == 2) ? (u32)QB_ALO : 0u);
                u32 bbase = smb + (u32)QB_B + ((split == 1) ? 32768u : 0u);
                u32 ka = (((u32)(ks * 8) + tka) ^ xsw) * 4;
                u32 kb = (((u32)(ks * 8) + tkb) ^ xsw) * 4;
                u32 af[2][4];
                ldsm4(af[0], abase + (u32)arow * 256 + ka);
                ldsm4(af[1], abase + (u32)(arow + 16) * 256 + ka);
#pragma unroll
                for (int np = 0; np < 2; np++) {
                    u32 bf[4];
                    ldsm4(bf, bbase + (u32)(brow_e + np * 16) * 256 + kb);
                    mma16816(acc[0][2 * np], af[0], bf[0], bf[1]);
                    mma16816(acc[0][2 * np + 1], af[0], bf[2], bf[3]);
                    mma16816(acc[1][2 * np], af[1], bf[0], bf[1]);
                    mma16816(acc[1][2 * np + 1], af[1], bf[2], bf[3]);
                }
            }
        }

#pragma unroll
        for (int mf = 0; mf < 2; mf++)
#pragma unroll
            for (int nf = 0; nf < 4; nf++) {
                int row = r0 + wm * 32 + mf * 16 + grp;
                int col = wn * 32 + nf * 8 + tid4 * 2;
                *(float2*)&g_bufA[(long long)row * 128 + col] =
                    make_float2(acc[mf][nf][0], acc[mf][nf][1]);
                *(float2*)&g_bufA[(long long)(row + 8) * 128 + col] =
                    make_float2(acc[mf][nf][2], acc[mf][nf][3]);
            }
    }

    // ---- barrier: h0 complete ----
    grid_bar(t, (unsigned)GCTAS_);

    // ================= PHASE 1..11: tree =================
    // B_w fill: W-split into QB_B (hi) / QB_B+40960 (lo).
    for (int j = t; j < 2 * 160 * 16; j += 256) {
        int split = j / 2560, rem = j - split * 2560;
        int row = rem >> 4, q = rem & 15;
        const __nv_bfloat16* src = split ? g_Wlo : g_Whi;
        u32 kpb = (u32)(4 * q) ^ ((row & 7) << 2);
        cp16(sm + QB_B + split * 40960 + (row * 64 + kpb) * 4,
             &src[(chunk * 160 + row) * 128 + q * 8]);
    }
    CP_COMMIT();
    float* bias_s = (float*)(sm + QB_BIAS);
    for (int j = t; j < 160; j += 256)
        bias_s[j] = 2.0f * bhh[(j >> 5) * 128 + chunk * 32 + (j & 31)];
    CP_WAIT0();
    __syncthreads();

    for (int lev = 1; lev <= 11; lev++) {
        int lg_nhalf = 11 - lev;
        int n_half = 1 << lg_nhalf;
        int ntiles = 2048 >> lev;
        const float* hin = (lev & 1) ? g_bufA : g_bufB;
        float* hout = (lev == 11) ? out_param : ((lev & 1) ? g_bufB : g_bufA);
        const float4* hin4 = (const float4*)hin;

        for (int tile = bx; tile < ntiles; tile += GX_) {
            int r0 = tile * 64;
            __syncthreads();

            for (int i = t; i < 64 * 32; i += 256) {
                int rr = i >> 5, c4 = i & 31;
                int r = r0 + rr;
                int b = r >> lg_nhalf;
                int iw = r - (b << lg_nhalf);
                long long base = (long long)b * (2 * n_half);
                float4 l4 = hin4[(base + 2 * iw) * 32 + c4];
                float4 r4 = hin4[(base + 2 * iw + 1) * 32 + c4];
                float xv[4] = {l4.x + r4.x, l4.y + r4.y, l4.z + r4.z, l4.w + r4.w};
                __nv_bfloat16 hi[4], lo[4];
#pragma unroll
                for (int j = 0; j < 4; j++) {
                    hi[j] = __float2bfloat16_rn(xv[j]);
                    lo[j] = __float2bfloat16_rn(xv[j] - __bfloat162float(hi[j]));
                }
                u32 sw = (u32)(2 * c4) ^ ((rr & 7) << 2);
                *(uint2*)(sm + (rr * 64 + sw) * 4) = *(uint2*)hi;
                *(uint2*)(sm + QB_ALO + (rr * 64 + sw) * 4) = *(uint2*)lo;
            }

            float2 hl_pre[2][2], hr_pre[2][2];
#pragma unroll
            for (int mf = 0; mf < 2; mf++)
#pragma unroll
                for (int half = 0; half < 2; half++) {
                    int rr = wm * 32 + mf * 16 + grp + half * 8;
                    int r = r0 + rr;
                    int b = r >> lg_nhalf;
                    int iw = r - (b << lg_nhalf);
                    long long rowL = (long long)b * (2 * n_half) + 2 * iw;
                    hl_pre[mf][half] = *(const float2*)&hin[rowL * 128 + hcol];
                    hr_pre[mf][half] = *(const float2*)&hin[(rowL + 1) * 128 + hcol];
                }
            __syncthreads();

            float acc[2][5][4];
#pragma unroll
            for (int a = 0; a < 2; a++)
#pragma unroll
                for (int g = 0; g < 5; g++)
#pragma unroll
                    for (int c = 0; c < 4; c++) acc[a][g][c] = 0.0f;

#pragma unroll 1
            for (int ks = 0; ks < 8; ks++) {
#pragma unroll
                for (int split = 0; split < 3; split++) {
                    u32 abase = smb + ((split == 2) ? (u32)QB_ALO : 0u);
                    u32 bbase = smb + QB_B + ((split == 1) ? 40960u : 0u);
                    u32 ka = (((u32)(ks * 8) + tka) ^ xsw) * 4;
                    u32 kb = (((u32)(ks * 8) + tkb) ^ xsw) * 4;
                    u32 af[2][4];
                    ldsm4(af[0], abase + (u32)arow * 256 + ka);
                    ldsm4(af[1], abase + (u32)(arow + 16) * 256 + ka);
                    u32 b01[4], b23[4], b4[2];
                    ldsm4(b01, bbase + (u32)((0 + bgsel) * 32 + rowB) * 256 + kb);
                    ldsm4(b23, bbase + (u32)((2 + bgsel) * 32 + rowB) * 256 + kb);
                    ldsm2(b4, bbase + (u32)(4 * 32 + rowB) * 256 + kb);
                    mma16816(acc[0][0], af[0], b01[0], b01[1]);
                    mma16816(acc[1][0], af[1], b01[0], b01[1]);
                    mma16816(acc[0][1], af[0], b01[2], b01[3]);
                    mma16816(acc[1][1], af[1], b01[2], b01[3]);
                    mma16816(acc[0][2], af[0], b23[0], b23[1]);
                    mma16816(acc[1][2], af[1], b23[0], b23[1]);
                    mma16816(acc[0][3], af[0], b23[2], b23[3]);
                    mma16816(acc[1][3], af[1], b23[2], b23[3]);
                    mma16816(acc[0][4], af[0], b4[0], b4[1]);
                    mma16816(acc[1][4], af[1], b4[0], b4[1]);
                }
            }

#pragma unroll
            for (int mf = 0; mf < 2; mf++) {
#pragma unroll
                for (int half = 0; half < 2; half++) {
                    int rr = wm * 32 + mf * 16 + grp + half * 8;
                    int r = r0 + rr;
                    float hl2[2] = {hl_pre[mf][half].x, hl_pre[mf][half].y};
                    float hr2[2] = {hr_pre[mf][half].x, hr_pre[mf][half].y};
                    float ov[2];
#pragma unroll
                    for (int j = 0; j < 2; j++) {
                        int e = half * 2 + j;
                        float si = acc[mf][0][e] + bias_s[0 * 32 + cl + j];
                        float sl = acc[mf][1][e] + bias_s[1 * 32 + cl + j];
                        float sr = acc[mf][2][e] + bias_s[2 * 32 + cl + j];
                        float so = acc[mf][3][e] + bias_s[3 * 32 + cl + j];
                        float sg = acc[mf][4][e] + bias_s[4 * 32 + cl + j];
                        float cc = sig_fast(si) * tanh_f(sg) + sig_fast(sl) * hl2[j] +
                                   sig_fast(sr) * hr2[j];
                        ov[j] = sig_fast(so) * tanh_f(cc);
                    }
                    *(float2*)&hout[(long long)r * 128 + hcol] = make_float2(ov[0], ov[1]);
                }
            }
        }

        if (lev < 11) grid_bar(t, (unsigned)(GCTAS_ * (lev + 1)));
    }
}

// ---------------- launcher ----------------
extern "C" void kernel_launch(void* const* d_in, const int* in_sizes, int n_in,
                              void* d_out, int out_size) {
    const int* ids = (const int*)d_in[0];
    const float* emb = (const float*)d_in[1];
    const float* Wwh = (const float*)d_in[2];
    const float* Whh = (const float*)d_in[3];
    const float* bhh = (const float*)d_in[4];
    float* out = (float*)d_out;

    cudaFuncSetAttribute(fused_all, cudaFuncAttributeMaxDynamicSharedMemorySize, QB_SM);

    prep_both<<<(128 * 640 + 128 * 128 + 255) / 256, 256>>>(Whh, Wwh);
    fused_all<<<dim3(GX_, 4), 256, QB_SM>>>(ids, emb, out, bhh);
}

// round 15
// speedup vs baseline: 1.0635x; 1.0009x over previous
#include <cuda_runtime.h>
#include <cuda_bf16.h>

#define BB_ 64
#define LL_ 2048
#define GX_ 74
#define GCTAS_ (GX_ * 4)

typedef unsigned long long ull;
typedef unsigned int u32;

// h ping-pong buffers (f32) for epilogue hl/hr reads.
__device__ float g_bufA[BB_ * LL_ * 128];        // 67 MB
__device__ float g_bufB[BB_ * (LL_ / 2) * 128];  // 33.5 MB
// Packed split-bf16 x buffers: x_L[row][col] = hl+hr as (hi | lo<<16).
__device__ u32 g_xO[BB_ * (LL_ / 2) * 128];      // odd levels  (33.5 MB)
__device__ u32 g_xE[BB_ * (LL_ / 4) * 128];      // even levels (16.7 MB)
// Permuted split W_hh: [chunk(4)][n(160)][k(128)] bf16, n = gate*32 + col
__device__ __align__(16) __nv_bfloat16 g_Whi[4 * 160 * 128];
__device__ __align__(16) __nv_bfloat16 g_Wlo[4 * 160 * 128];
// Split W_wh transposed: [n(128)][k(128)]
__device__ __align__(16) __nv_bfloat16 g_Ehi[128 * 128];
__device__ __align__(16) __nv_bfloat16 g_Elo[128 * 128];
// Device-wide barrier counter (reset by prep_both every replay).
__device__ unsigned g_bar;

extern __shared__ float smem[];

// ---------------- scalar helpers ----------------
__device__ __forceinline__ float tanhfast(float x) {
    float y; asm("tanh.approx.f32 %0, %1;" : "=f"(y) : "f"(x)); return y;
}
__device__ __forceinline__ float sig_fast(float x) {
    return fmaf(0.5f, tanhfast(0.5f * x), 0.5f);
}
__device__ __forceinline__ float tanh_f(float x) {
    return 1.0f - 2.0f / (__expf(2.0f * x) + 1.0f);
}
// Pack f32 -> (bf16_hi | bf16_lo << 16), rn split.
__device__ __forceinline__ u32 pkx(float x) {
    __nv_bfloat16 hi = __float2bfloat16_rn(x);
    __nv_bfloat16 lo = __float2bfloat16_rn(x - __bfloat162float(hi));
    u32 h16 = (u32) * (unsigned short*)&hi;
    u32 l16 = (u32) * (unsigned short*)&lo;
    return h16 | (l16 << 16);
}

// ---------------- cp.async ----------------
__device__ __forceinline__ void cp16(void* s, const void* g) {
    unsigned a = (unsigned)__cvta_generic_to_shared(s);
    asm volatile("cp.async.cg.shared.global [%0], [%1], 16;" :: "r"(a), "l"(g));
}
#define CP_COMMIT() asm volatile("cp.async.commit_group;")
#define CP_WAIT0()  asm volatile("cp.async.wait_group 0;")

// ---------------- mma.sync helpers ----------------
__device__ __forceinline__ u32 smem_u32(const void* p) {
    u32 a;
    asm("{ .reg .u64 t; cvta.to.shared.u64 t, %1; cvt.u32.u64 %0, t; }" : "=r"(a) : "l"(p));
    return a;
}
__device__ __forceinline__ void ldsm4(u32* r, u32 saddr) {
    asm volatile("ldmatrix.sync.aligned.m8n8.x4.shared.b16 {%0,%1,%2,%3}, [%4];"
                 : "=r"(r[0]), "=r"(r[1]), "=r"(r[2]), "=r"(r[3]) : "r"(saddr));
}
__device__ __forceinline__ void ldsm2(u32* r, u32 saddr) {
    asm volatile("ldmatrix.sync.aligned.m8n8.x2.shared.b16 {%0,%1}, [%2];"
                 : "=r"(r[0]), "=r"(r[1]) : "r"(saddr));
}
__device__ __forceinline__ void mma16816(float* d, const u32* a, u32 b0, u32 b1) {
    asm volatile(
        "mma.sync.aligned.m16n8k16.row.col.f32.bf16.bf16.f32 "
        "{%0,%1,%2,%3}, {%4,%5,%6,%7}, {%8,%9}, {%0,%1,%2,%3};"
        : "+f"(d[0]), "+f"(d[1]), "+f"(d[2]), "+f"(d[3])
        : "r"(a[0]), "r"(a[1]), "r"(a[2]), "r"(a[3]), "r"(b0), "r"(b1));
}

// =====================================================================
// Prep (single launch): split weights to bf16 hi/lo; reset barrier.
// =====================================================================
__global__ void prep_both(const float* __restrict__ Whh, const float* __restrict__ Wwh) {
    int idx = blockIdx.x * 256 + threadIdx.x;
    if (idx == 0) g_bar = 0u;
    if (idx < 128 * 640) {
        int k = idx / 640, col = idx - k * 640;
        int g = col >> 7, c = col & 127;
        int chunk = c >> 5, cl = c & 31;
        int n = g * 32 + cl;
        float w = Whh[idx];
        __nv_bfloat16 hi = __float2bfloat16_rn(w);
        __nv_bfloat16 lo = __float2bfloat16_rn(w - __bfloat162float(hi));
        int dst = (chunk * 160 + n) * 128 + k;
        g_Whi[dst] = hi;
        g_Wlo[dst] = lo;
    } else if (idx < 128 * 640 + 128 * 128) {
        int e = idx - 128 * 640;
        int k = e >> 7, n = e & 127;
        float w = Wwh[e];
        __nv_bfloat16 hi = __float2bfloat16_rn(w);
        __nv_bfloat16 lo = __float2bfloat16_rn(w - __bfloat162float(hi));
        g_Ehi[n * 128 + k] = hi;
        g_Elo[n * 128 + k] = lo;
    }
}

// =====================================================================
// MEGA-KERNEL: embed (level 0) + all 11 tree levels in ONE launch.
// Grid fixed (74,4) = 296 CTAs = 2/SM x 148. Grid barrier between levels.
// Producer-side x: each level's epilogue writes packed split-bf16
// x = h_even + h_odd (shfl pairing); next level's fill is LDG+PRMT only.
// smem: A 2x16KB | B 2x40KB | bias 640B = 115328 B -> 2 CTAs/SM.
// =====================================================================
#define QB_ALO 16384
#define QB_B 32768
#define QB_BIAS 114688
#define QB_SM 115328

__device__ __forceinline__ void grid_bar(int t, unsigned target) {
    __threadfence();   // release
    __syncthreads();
    if (t == 0) {
        atomicAdd(&g_bar, 1u);
        while (atomicAdd(&g_bar, 0u) < target) __nanosleep(64);
    }
    __syncthreads();
    __threadfence();   // acquire
}

__global__ __launch_bounds__(256, 2) void fused_all(const int* __restrict__ ids,
                                                    const float* __restrict__ emb,
                                                    float* __restrict__ out_param,
                                                    const float* __restrict__ bhh) {
    char* sm = (char*)smem;
    int t = threadIdx.x;
    int chunk = blockIdx.y;
    int bx = blockIdx.x;
    int flat = chunk * GX_ + bx;

    u32 smb = smem_u32(sm);
    int lane = t & 31, warp = t >> 5;
    int wm = warp >> 2, wn = warp & 3;  // 2 x 4
    int t8 = lane >> 3, l7 = lane & 7;
    u32 xsw = (u32)(l7 << 2);
    int arow = wm * 32 + (t8 & 1) * 8 + l7;
    u32 tka = (u32)((t8 >> 1) * 4);
    u32 tkb = (u32)((t8 & 1) * 4);
    int grp = lane >> 2, tid4 = lane & 3;
    int grp_even = !(grp & 1);
    // embed B mapping (N=128 across 4 warps)
    int brow_e = wn * 32 + (t8 >> 1) * 8 + l7;
    // tree B mapping (gate-aligned)
    int rowB = wn * 8 + l7;
    int bgsel = t8 >> 1;
    int cl = wn * 8 + tid4 * 2;
    int hcol = chunk * 32 + cl;

    // ================= PHASE 0: embed =================
    for (int j = t; j < 2 * 128 * 16; j += 256) {
        int split = j >> 11, rem = j & 2047;
        int row = rem >> 4, q = rem & 15;
        const __nv_bfloat16* src = split ? g_Elo : g_Ehi;
        u32 kpb = (u32)(4 * q) ^ ((row & 7) << 2);
        cp16(sm + QB_B + split * 32768 + (row * 64 + kpb) * 4, &src[row * 128 + q * 8]);
    }
    CP_COMMIT();

    for (int tile = flat; tile < 2048; tile += GCTAS_) {
        int r0 = tile * 64;
        __syncthreads();

        for (int i = t; i < 64 * 32; i += 256) {
            int rr = i >> 5, c4 = i & 31;
            int id = ids[r0 + rr];
            float4 v = ((const float4*)emb)[(long long)id * 32 + c4];
            float xv[4] = {v.x, v.y, v.z, v.w};
            __nv_bfloat16 hi[4], lo[4];
#pragma unroll
            for (int j = 0; j < 4; j++) {
                hi[j] = __float2bfloat16_rn(xv[j]);
                lo[j] = __float2bfloat16_rn(xv[j] - __bfloat162float(hi[j]));
            }
            u32 sw = (u32)(2 * c4) ^ ((rr & 7) << 2);
            *(uint2*)(sm + (rr * 64 + sw) * 4) = *(uint2*)hi;
            *(uint2*)(sm + QB_ALO + (rr * 64 + sw) * 4) = *(uint2*)lo;
        }
        CP_WAIT0();
        __syncthreads();

        float acc[2][4][4];
#pragma unroll
        for (int a = 0; a < 2; a++)
#pragma unroll
            for (int b = 0; b < 4; b++)
#pragma unroll
                for (int c = 0; c < 4; c++) acc[a][b][c] = 0.0f;

#pragma unroll 1
        for (int ks = 0; ks < 8; ks++) {
#pragma unroll
            for (int split = 0; split < 3; split++) {
                u32 abase = smb + ((split == 2) ? (u32)QB_ALO : 0u);
                u32 bbase = smb + (u32)QB_B + ((split == 1) ? 32768u : 0u);
                u32 ka = (((u32)(ks * 8) + tka) ^ xsw) * 4;
                u32 kb = (((u32)(ks * 8) + tkb) ^ xsw) * 4;
                u32 af[2][4];
                ldsm4(af[0], abase + (u32)arow * 256 + ka);
                ldsm4(af[1], abase + (u32)(arow + 16) * 256 + ka);
#pragma unroll
                for (int np = 0; np < 2; np++) {
                    u32 bf[4];
                    ldsm4(bf, bbase + (u32)(brow_e + np * 16) * 256 + kb);
                    mma16816(acc[0][2 * np], af[0], bf[0], bf[1]);
                    mma16816(acc[0][2 * np + 1], af[0], bf[2], bf[3]);
                    mma16816(acc[1][2 * np], af[1], bf[0], bf[1]);
                    mma16816(acc[1][2 * np + 1], af[1], bf[2], bf[3]);
                }
            }
        }

        // Epilogue: write h0 (f32) AND packed x_1 = h0[2j]+h0[2j+1].
#pragma unroll
        for (int mf = 0; mf < 2; mf++)
#pragma unroll
            for (int nf = 0; nf < 4; nf++) {
                int row = r0 + wm * 32 + mf * 16 + grp;
                int col = wn * 32 + nf * 8 + tid4 * 2;
                *(float2*)&g_bufA[(long long)row * 128 + col] =
                    make_float2(acc[mf][nf][0], acc[mf][nf][1]);
                *(float2*)&g_bufA[(long long)(row + 8) * 128 + col] =
                    make_float2(acc[mf][nf][2], acc[mf][nf][3]);
                float p0 = __shfl_down_sync(0xffffffffu, acc[mf][nf][0], 4);
                float p1 = __shfl_down_sync(0xffffffffu, acc[mf][nf][1], 4);
                float p2 = __shfl_down_sync(0xffffffffu, acc[mf][nf][2], 4);
                float p3 = __shfl_down_sync(0xffffffffu, acc[mf][nf][3], 4);
                if (grp_even) {
                    long long xr = (long long)(row >> 1) * 128 + col;
                    *(uint2*)&g_xO[xr] =
                        make_uint2(pkx(acc[mf][nf][0] + p0), pkx(acc[mf][nf][1] + p1));
                    *(uint2*)&g_xO[xr + 4 * 128] =
                        make_uint2(pkx(acc[mf][nf][2] + p2), pkx(acc[mf][nf][3] + p3));
                }
            }
    }

    grid_bar(t, (unsigned)GCTAS_);

    // ================= PHASE 1..11: tree =================
    for (int j = t; j < 2 * 160 * 16; j += 256) {
        int split = j / 2560, rem = j - split * 2560;
        int row = rem >> 4, q = rem & 15;
        const __nv_bfloat16* src = split ? g_Wlo : g_Whi;
        u32 kpb = (u32)(4 * q) ^ ((row & 7) << 2);
        cp16(sm + QB_B + split * 40960 + (row * 64 + kpb) * 4,
             &src[(chunk * 160 + row) * 128 + q * 8]);
    }
    CP_COMMIT();
    float* bias_s = (float*)(sm + QB_BIAS);
    for (int j = t; j < 160; j += 256)
        bias_s[j] = 2.0f * bhh[(j >> 5) * 128 + chunk * 32 + (j & 31)];
    CP_WAIT0();
    __syncthreads();

    for (int lev = 1; lev <= 11; lev++) {
        int lg_nhalf = 11 - lev;
        int n_half = 1 << lg_nhalf;
        int ntiles = 2048 >> lev;
        const float* hin = (lev & 1) ? g_bufA : g_bufB;
        float* hout = (lev == 11) ? out_param : ((lev & 1) ? g_bufB : g_bufA);
        const uint4* xin4 = (const uint4*)((lev & 1) ? g_xO : g_xE);
        u32* xout = (lev & 1) ? g_xE : g_xO;

        for (int tile = bx; tile < ntiles; tile += GX_) {
            int r0 = tile * 64;
            __syncthreads();

            // A fill: packed x -> PRMT unpack -> swizzled smem.
            for (int i = t; i < 64 * 32; i += 256) {
                int rr = i >> 5, c4 = i & 31;
                uint4 p = xin4[(long long)(r0 + rr) * 32 + c4];
                u32 hi01 = __byte_perm(p.x, p.y, 0x5410);
                u32 lo01 = __byte_perm(p.x, p.y, 0x7632);
                u32 hi23 = __byte_perm(p.z, p.w, 0x5410);
                u32 lo23 = __byte_perm(p.z, p.w, 0x7632);
                u32 sw = (u32)(2 * c4) ^ ((rr & 7) << 2);
                *(uint2*)(sm + (rr * 64 + sw) * 4) = make_uint2(hi01, hi23);
                *(uint2*)(sm + QB_ALO + (rr * 64 + sw) * 4) = make_uint2(lo01, lo23);
            }

            // Prefetch epilogue operands (hl/hr f32).
            float2 hl_pre[2][2], hr_pre[2][2];
#pragma unroll
            for (int mf = 0; mf < 2; mf++)
#pragma unroll
                for (int half = 0; half < 2; half++) {
                    int rr = wm * 32 + mf * 16 + grp + half * 8;
                    int r = r0 + rr;
                    int b = r >> lg_nhalf;
                    int iw = r - (b << lg_nhalf);
                    long long rowL = (long long)b * (2 * n_half) + 2 * iw;
                    hl_pre[mf][half] = *(const float2*)&hin[rowL * 128 + hcol];
                    hr_pre[mf][half] = *(const float2*)&hin[(rowL + 1) * 128 + hcol];
                }
            __syncthreads();

            float acc[2][5][4];
#pragma unroll
            for (int a = 0; a < 2; a++)
#pragma unroll
                for (int g = 0; g < 5; g++)
#pragma unroll
                    for (int c = 0; c < 4; c++) acc[a][g][c] = 0.0f;

#pragma unroll 1
            for (int ks = 0; ks < 8; ks++) {
#pragma unroll
                for (int split = 0; split < 3; split++) {
                    u32 abase = smb + ((split == 2) ? (u32)QB_ALO : 0u);
                    u32 bbase = smb + QB_B + ((split == 1) ? 40960u : 0u);
                    u32 ka = (((u32)(ks * 8) + tka) ^ xsw) * 4;
                    u32 kb = (((u32)(ks * 8) + tkb) ^ xsw) * 4;
                    u32 af[2][4];
                    ldsm4(af[0], abase + (u32)arow * 256 + ka);
                    ldsm4(af[1], abase + (u32)(arow + 16) * 256 + ka);
                    u32 b01[4], b23[4], b4[2];
                    ldsm4(b01, bbase + (u32)((0 + bgsel) * 32 + rowB) * 256 + kb);
                    ldsm4(b23, bbase + (u32)((2 + bgsel) * 32 + rowB) * 256 + kb);
                    ldsm2(b4, bbase + (u32)(4 * 32 + rowB) * 256 + kb);
                    mma16816(acc[0][0], af[0], b01[0], b01[1]);
                    mma16816(acc[1][0], af[1], b01[0], b01[1]);
                    mma16816(acc[0][1], af[0], b01[2], b01[3]);
                    mma16816(acc[1][1], af[1], b01[2], b01[3]);
                    mma16816(acc[0][2], af[0], b23[0], b23[1]);
                    mma16816(acc[1][2], af[1], b23[0], b23[1]);
                    mma16816(acc[0][3], af[0], b23[2], b23[3]);
                    mma16816(acc[1][3], af[1], b23[2], b23[3]);
                    mma16816(acc[0][4], af[0], b4[0], b4[1]);
                    mma16816(acc[1][4], af[1], b4[0], b4[1]);
                }
            }

            // Epilogue: LSTM; write h (f32) and packed x for next level.
#pragma unroll
            for (int mf = 0; mf < 2; mf++) {
#pragma unroll
                for (int half = 0; half < 2; half++) {
                    int rr = wm * 32 + mf * 16 + grp + half * 8;
                    int r = r0 + rr;
                    float hl2[2] = {hl_pre[mf][half].x, hl_pre[mf][half].y};
                    float hr2[2] = {hr_pre[mf][half].x, hr_pre[mf][half].y};
                    float ov[2];
#pragma unroll
                    for (int j = 0; j < 2; j++) {
                        int e = half * 2 + j;
                        float si = acc[mf][0][e] + bias_s[0 * 32 + cl + j];
                        float sl = acc[mf][1][e] + bias_s[1 * 32 + cl + j];
                        float sr = acc[mf][2][e] + bias_s[2 * 32 + cl + j];
                        float so = acc[mf][3][e] + bias_s[3 * 32 + cl + j];
                        float sg = acc[mf][4][e] + bias_s[4 * 32 + cl + j];
                        float cc = sig_fast(si) * tanh_f(sg) + sig_fast(sl) * hl2[j] +
                                   sig_fast(sr) * hr2[j];
                        ov[j] = sig_fast(so) * tanh_f(cc);
                    }
                    *(float2*)&hout[(long long)r * 128 + hcol] = make_float2(ov[0], ov[1]);
                    if (lev < 11) {
                        float p0 = __shfl_down_sync(0xffffffffu, ov[0], 4);
                        float p1 = __shfl_down_sync(0xffffffffu, ov[1], 4);
                        if (grp_even) {
                            long long xr = (long long)(r >> 1) * 128 + hcol;
                            *(uint2*)&xout[xr] =
                                make_uint2(pkx(ov[0] + p0), pkx(ov[1] + p1));
                        }
                    }
                }
            }
        }

        if (lev < 11) grid_bar(t, (unsigned)(GCTAS_ * (lev + 1)));
    }
}

// ---------------- launcher ----------------
extern "C" void kernel_launch(void* const* d_in, const int* in_sizes, int n_in,
                              void* d_out, int out_size) {
    const int* ids = (const int*)d_in[0];
    const float* emb = (const float*)d_in[1];
    const float* Wwh = (const float*)d_in[2];
    const float* Whh = (const float*)d_in[3];
    const float* bhh = (const float*)d_in[4];
    float* out = (float*)d_out;

    cudaFuncSetAttribute(fused_all, cudaFuncAttributeMaxDynamicSharedMemorySize, QB_SM);

    prep_both<<<(128 * 640 + 128 * 128 + 255) / 256, 256>>>(Whh, Wwh);
    fused_all<<<dim3(GX_, 4), 256, QB_SM>>>(ids, emb, out, bhh);
}

// round 16
// speedup vs baseline: 1.0745x; 1.0103x over previous
#include <cuda_runtime.h>
#include <cuda_bf16.h>

#define BB_ 64
#define LL_ 2048
#define GX_ 74
#define GCTAS_ (GX_ * 4)

typedef unsigned long long ull;
typedef unsigned int u32;

// h ping-pong buffers (f32) for epilogue hl/hr reads.
__device__ float g_bufA[BB_ * LL_ * 128];        // 67 MB
__device__ float g_bufB[BB_ * (LL_ / 2) * 128];  // 33.5 MB
// x buffers in SMEM-IMAGE layout: per 64-row tile, 8192 u32 =
// [hi plane 4096 u32][lo plane 4096 u32], swizzled exactly like A smem.
__device__ u32 g_xO[BB_ * (LL_ / 2) * 128];      // odd-level inputs  (33.5 MB)
__device__ u32 g_xE[BB_ * (LL_ / 4) * 128];      // even-level inputs (16.7 MB)
// Permuted split W_hh: [chunk(4)][n(160)][k(128)] bf16, n = gate*32 + col
__device__ __align__(16) __nv_bfloat16 g_Whi[4 * 160 * 128];
__device__ __align__(16) __nv_bfloat16 g_Wlo[4 * 160 * 128];
// Split W_wh transposed: [n(128)][k(128)]
__device__ __align__(16) __nv_bfloat16 g_Ehi[128 * 128];
__device__ __align__(16) __nv_bfloat16 g_Elo[128 * 128];
// Device-wide barrier counter (reset by prep_both every replay).
__device__ unsigned g_bar;

extern __shared__ float smem[];

// ---------------- scalar helpers ----------------
__device__ __forceinline__ float tanhfast(float x) {
    float y; asm("tanh.approx.f32 %0, %1;" : "=f"(y) : "f"(x)); return y;
}
__device__ __forceinline__ float sig_fast(float x) {
    return fmaf(0.5f, tanhfast(0.5f * x), 0.5f);
}
__device__ __forceinline__ float tanh_f(float x) {
    return 1.0f - 2.0f / (__expf(2.0f * x) + 1.0f);
}

// Write x pair (cols col, col+1 of row2) into plane-layout x buffer.
// idx mirrors the A-smem swizzle: u32 index = rr*64 + (2*c4 ^ ((rr&7)<<2)) + j.
__device__ __forceinline__ void write_x(u32* xout, long long row2, int col,
                                        float x0, float x1) {
    int tl = (int)(row2 >> 6);
    int rr = (int)(row2 & 63);
    int c4 = col >> 2, j = (col >> 1) & 1;
    u32 idx = (u32)(rr * 64 + ((2 * c4) ^ ((rr & 7) << 2)) + j);
    long long base = (long long)tl * 8192;
    __nv_bfloat16 h0 = __float2bfloat16_rn(x0);
    __nv_bfloat16 h1 = __float2bfloat16_rn(x1);
    __nv_bfloat16 l0 = __float2bfloat16_rn(x0 - __bfloat162float(h0));
    __nv_bfloat16 l1 = __float2bfloat16_rn(x1 - __bfloat162float(h1));
    u32 hiw = (u32)(*(unsigned short*)&h0) | ((u32)(*(unsigned short*)&h1) << 16);
    u32 low = (u32)(*(unsigned short*)&l0) | ((u32)(*(unsigned short*)&l1) << 16);
    xout[base + idx] = hiw;
    xout[base + 4096 + idx] = low;
}

// ---------------- cp.async ----------------
__device__ __forceinline__ void cp16(void* s, const void* g) {
    unsigned a = (unsigned)__cvta_generic_to_shared(s);
    asm volatile("cp.async.cg.shared.global [%0], [%1], 16;" :: "r"(a), "l"(g));
}
#define CP_COMMIT() asm volatile("cp.async.commit_group;")
#define CP_WAIT0()  asm volatile("cp.async.wait_group 0;")

// ---------------- mma.sync helpers ----------------
__device__ __forceinline__ u32 smem_u32(const void* p) {
    u32 a;
    asm("{ .reg .u64 t; cvta.to.shared.u64 t, %1; cvt.u32.u64 %0, t; }" : "=r"(a) : "l"(p));
    return a;
}
__device__ __forceinline__ void ldsm4(u32* r, u32 saddr) {
    asm volatile("ldmatrix.sync.aligned.m8n8.x4.shared.b16 {%0,%1,%2,%3}, [%4];"
                 : "=r"(r[0]), "=r"(r[1]), "=r"(r[2]), "=r"(r[3]) : "r"(saddr));
}
__device__ __forceinline__ void ldsm2(u32* r, u32 saddr) {
    asm volatile("ldmatrix.sync.aligned.m8n8.x2.shared.b16 {%0,%1}, [%2];"
                 : "=r"(r[0]), "=r"(r[1]) : "r"(saddr));
}
__device__ __forceinline__ void mma16816(float* d, const u32* a, u32 b0, u32 b1) {
    asm volatile(
        "mma.sync.aligned.m16n8k16.row.col.f32.bf16.bf16.f32 "
        "{%0,%1,%2,%3}, {%4,%5,%6,%7}, {%8,%9}, {%0,%1,%2,%3};"
        : "+f"(d[0]), "+f"(d[1]), "+f"(d[2]), "+f"(d[3])
        : "r"(a[0]), "r"(a[1]), "r"(a[2]), "r"(a[3]), "r"(b0), "r"(b1));
}

// =====================================================================
// Prep (single launch): split weights to bf16 hi/lo; reset barrier.
// =====================================================================
__global__ void prep_both(const float* __restrict__ Whh, const float* __restrict__ Wwh) {
    int idx = blockIdx.x * 256 + threadIdx.x;
    if (idx == 0) g_bar = 0u;
    if (idx < 128 * 640) {
        int k = idx / 640, col = idx - k * 640;
        int g = col >> 7, c = col & 127;
        int chunk = c >> 5, cl = c & 31;
        int n = g * 32 + cl;
        float w = Whh[idx];
        __nv_bfloat16 hi = __float2bfloat16_rn(w);
        __nv_bfloat16 lo = __float2bfloat16_rn(w - __bfloat162float(hi));
        int dst = (chunk * 160 + n) * 128 + k;
        g_Whi[dst] = hi;
        g_Wlo[dst] = lo;
    } else if (idx < 128 * 640 + 128 * 128) {
        int e = idx - 128 * 640;
        int k = e >> 7, n = e & 127;
        float w = Wwh[e];
        __nv_bfloat16 hi = __float2bfloat16_rn(w);
        __nv_bfloat16 lo = __float2bfloat16_rn(w - __bfloat162float(hi));
        g_Ehi[n * 128 + k] = hi;
        g_Elo[n * 128 + k] = lo;
    }
}

// =====================================================================
// MEGA-KERNEL: embed + 11 tree levels, one launch, grid (74,4) = 296
// CTAs = 2/SM x 148. x buffers are pre-swizzled smem images, so each
// tree-level A-fill is a pure cp.async memcpy issued BEFORE the
// epilogue -> fill latency hides behind epilogue + the co-resident CTA.
// smem: A 2x16KB | B 2x40KB | bias 640B = 115328 B -> 2 CTAs/SM.
// =====================================================================
#define QB_ALO 16384
#define QB_B 32768
#define QB_BIAS 114688
#define QB_SM 115328

__device__ __forceinline__ void grid_bar(int t, unsigned target) {
    __threadfence();   // release
    __syncthreads();
    if (t == 0) {
        atomicAdd(&g_bar, 1u);
        while (atomicAdd(&g_bar, 0u) < target) __nanosleep(64);
    }
    __syncthreads();
    __threadfence();   // acquire
}

__global__ __launch_bounds__(256, 2) void fused_all(const int* __restrict__ ids,
                                                    const float* __restrict__ emb,
                                                    float* __restrict__ out_param,
                                                    const float* __restrict__ bhh) {
    char* sm = (char*)smem;
    int t = threadIdx.x;
    int chunk = blockIdx.y;
    int bx = blockIdx.x;
    int flat = chunk * GX_ + bx;

    u32 smb = smem_u32(sm);
    int lane = t & 31, warp = t >> 5;
    int wm = warp >> 2, wn = warp & 3;  // 2 x 4
    int t8 = lane >> 3, l7 = lane & 7;
    u32 xsw = (u32)(l7 << 2);
    int arow = wm * 32 + (t8 & 1) * 8 + l7;
    u32 tka = (u32)((t8 >> 1) * 4);
    u32 tkb = (u32)((t8 & 1) * 4);
    int grp = lane >> 2, tid4 = lane & 3;
    int grp_even = !(grp & 1);
    int brow_e = wn * 32 + (t8 >> 1) * 8 + l7;  // embed B mapping
    int rowB = wn * 8 + l7;                     // tree B mapping (gate-aligned)
    int bgsel = t8 >> 1;
    int cl = wn * 8 + tid4 * 2;
    int hcol = chunk * 32 + cl;

    // Pure-memcpy A fill from plane-layout x buffer (no regs, no ALU).
    auto fillA = [&](const u32* xin, int tl) {
        const u32* src = xin + (long long)tl * 8192;
#pragma unroll
        for (int j4 = 0; j4 < 4; j4++) {
            int j = t + j4 * 256;  // 0..1023 uint4 per plane
            cp16(sm + j * 16, src + j * 4);
            cp16(sm + QB_ALO + j * 16, src + 4096 + j * 4);
        }
        CP_COMMIT();
    };

    // ================= PHASE 0: embed =================
    for (int j = t; j < 2 * 128 * 16; j += 256) {
        int split = j >> 11, rem = j & 2047;
        int row = rem >> 4, q = rem & 15;
        const __nv_bfloat16* src = split ? g_Elo : g_Ehi;
        u32 kpb = (u32)(4 * q) ^ ((row & 7) << 2);
        cp16(sm + QB_B + split * 32768 + (row * 64 + kpb) * 4, &src[row * 128 + q * 8]);
    }
    CP_COMMIT();

    for (int tile = flat; tile < 2048; tile += GCTAS_) {
        int r0 = tile * 64;
        __syncthreads();

        for (int i = t; i < 64 * 32; i += 256) {
            int rr = i >> 5, c4 = i & 31;
            int id = ids[r0 + rr];
            float4 v = ((const float4*)emb)[(long long)id * 32 + c4];
            float xv[4] = {v.x, v.y, v.z, v.w};
            __nv_bfloat16 hi[4], lo[4];
#pragma unroll
            for (int j = 0; j < 4; j++) {
                hi[j] = __float2bfloat16_rn(xv[j]);
                lo[j] = __float2bfloat16_rn(xv[j] - __bfloat162float(hi[j]));
            }
            u32 sw = (u32)(2 * c4) ^ ((rr & 7) << 2);
            *(uint2*)(sm + (rr * 64 + sw) * 4) = *(uint2*)hi;
            *(uint2*)(sm + QB_ALO + (rr * 64 + sw) * 4) = *(uint2*)lo;
        }
        CP_WAIT0();
        __syncthreads();

        float acc[2][4][4];
#pragma unroll
        for (int a = 0; a < 2; a++)
#pragma unroll
            for (int b = 0; b < 4; b++)
#pragma unroll
                for (int c = 0; c < 4; c++) acc[a][b][c] = 0.0f;

#pragma unroll 1
        for (int ks = 0; ks < 8; ks++) {
#pragma unroll
            for (int split = 0; split < 3; split++) {
                u32 abase = smb + ((split == 2) ? (u32)QB_ALO : 0u);
                u32 bbase = smb + (u32)QB_B + ((split == 1) ? 32768u : 0u);
                u32 ka = (((u32)(ks * 8) + tka) ^ xsw) * 4;
                u32 kb = (((u32)(ks * 8) + tkb) ^ xsw) * 4;
                u32 af[2][4];
                ldsm4(af[0], abase + (u32)arow * 256 + ka);
                ldsm4(af[1], abase + (u32)(arow + 16) * 256 + ka);
#pragma unroll
                for (int np = 0; np < 2; np++) {
                    u32 bf[4];
                    ldsm4(bf, bbase + (u32)(brow_e + np * 16) * 256 + kb);
                    mma16816(acc[0][2 * np], af[0], bf[0], bf[1]);
                    mma16816(acc[0][2 * np + 1], af[0], bf[2], bf[3]);
                    mma16816(acc[1][2 * np], af[1], bf[0], bf[1]);
                    mma16816(acc[1][2 * np + 1], af[1], bf[2], bf[3]);
                }
            }
        }

        // Epilogue: h0 (f32) + x_1 planes.
#pragma unroll
        for (int mf = 0; mf < 2; mf++)
#pragma unroll
            for (int nf = 0; nf < 4; nf++) {
                int row = r0 + wm * 32 + mf * 16 + grp;
                int col = wn * 32 + nf * 8 + tid4 * 2;
                *(float2*)&g_bufA[(long long)row * 128 + col] =
                    make_float2(acc[mf][nf][0], acc[mf][nf][1]);
                *(float2*)&g_bufA[(long long)(row + 8) * 128 + col] =
                    make_float2(acc[mf][nf][2], acc[mf][nf][3]);
                float p0 = __shfl_down_sync(0xffffffffu, acc[mf][nf][0], 4);
                float p1 = __shfl_down_sync(0xffffffffu, acc[mf][nf][1], 4);
                float p2 = __shfl_down_sync(0xffffffffu, acc[mf][nf][2], 4);
                float p3 = __shfl_down_sync(0xffffffffu, acc[mf][nf][3], 4);
                if (grp_even) {
                    write_x(g_xO, (long long)(row >> 1), col,
                            acc[mf][nf][0] + p0, acc[mf][nf][1] + p1);
                    write_x(g_xO, (long long)((row + 8) >> 1), col,
                            acc[mf][nf][2] + p2, acc[mf][nf][3] + p3);
                }
            }
    }

    grid_bar(t, (unsigned)GCTAS_);

    // ================= PHASE 1..11: tree =================
    for (int j = t; j < 2 * 160 * 16; j += 256) {
        int split = j / 2560, rem = j - split * 2560;
        int row = rem >> 4, q = rem & 15;
        const __nv_bfloat16* src = split ? g_Wlo : g_Whi;
        u32 kpb = (u32)(4 * q) ^ ((row & 7) << 2);
        cp16(sm + QB_B + split * 40960 + (row * 64 + kpb) * 4,
             &src[(chunk * 160 + row) * 128 + q * 8]);
    }
    CP_COMMIT();
    float* bias_s = (float*)(sm + QB_BIAS);
    for (int j = t; j < 160; j += 256)
        bias_s[j] = 2.0f * bhh[(j >> 5) * 128 + chunk * 32 + (j & 31)];
    CP_WAIT0();
    __syncthreads();

    for (int lev = 1; lev <= 11; lev++) {
        int lg_nhalf = 11 - lev;
        int n_half = 1 << lg_nhalf;
        int ntiles = 2048 >> lev;
        const float* hin = (lev & 1) ? g_bufA : g_bufB;
        float* hout = (lev == 11) ? out_param : ((lev & 1) ? g_bufB : g_bufA);
        const u32* xin = (lev & 1) ? g_xO : g_xE;
        u32* xout = (lev & 1) ? g_xE : g_xO;

        int tile = bx;
        if (tile < ntiles) fillA(xin, tile);  // prologue fill

        for (; tile < ntiles; tile += GX_) {
            int r0 = tile * 64;

            // Prefetch epilogue operands (hl/hr f32) — overlaps cp wait.
            float2 hl_pre[2][2], hr_pre[2][2];
#pragma unroll
            for (int mf = 0; mf < 2; mf++)
#pragma unroll
                for (int half = 0; half < 2; half++) {
                    int rr = wm * 32 + mf * 16 + grp + half * 8;
                    int r = r0 + rr;
                    int b = r >> lg_nhalf;
                    int iw = r - (b << lg_nhalf);
                    long long rowL = (long long)b * (2 * n_half) + 2 * iw;
                    hl_pre[mf][half] = *(const float2*)&hin[rowL * 128 + hcol];
                    hr_pre[mf][half] = *(const float2*)&hin[(rowL + 1) * 128 + hcol];
                }

            CP_WAIT0();     // A planes landed
            __syncthreads();

            float acc[2][5][4];
#pragma unroll
            for (int a = 0; a < 2; a++)
#pragma unroll
                for (int g = 0; g < 5; g++)
#pragma unroll
                    for (int c = 0; c < 4; c++) acc[a][g][c] = 0.0f;

#pragma unroll 1
            for (int ks = 0; ks < 8; ks++) {
#pragma unroll
                for (int split = 0; split < 3; split++) {
                    u32 abase = smb + ((split == 2) ? (u32)QB_ALO : 0u);
                    u32 bbase = smb + QB_B + ((split == 1) ? 40960u : 0u);
                    u32 ka = (((u32)(ks * 8) + tka) ^ xsw) * 4;
                    u32 kb = (((u32)(ks * 8) + tkb) ^ xsw) * 4;
                    u32 af[2][4];
                    ldsm4(af[0], abase + (u32)arow * 256 + ka);
                    ldsm4(af[1], abase + (u32)(arow + 16) * 256 + ka);
                    u32 b01[4], b23[4], b4[2];
                    ldsm4(b01, bbase + (u32)((0 + bgsel) * 32 + rowB) * 256 + kb);
                    ldsm4(b23, bbase + (u32)((2 + bgsel) * 32 + rowB) * 256 + kb);
                    ldsm2(b4, bbase + (u32)(4 * 32 + rowB) * 256 + kb);
                    mma16816(acc[0][0], af[0], b01[0], b01[1]);
                    mma16816(acc[1][0], af[1], b01[0], b01[1]);
                    mma16816(acc[0][1], af[0], b01[2], b01[3]);
                    mma16816(acc[1][1], af[1], b01[2], b01[3]);
                    mma16816(acc[0][2], af[0], b23[0], b23[1]);
                    mma16816(acc[1][2], af[1], b23[0], b23[1]);
                    mma16816(acc[0][3], af[0], b23[2], b23[3]);
                    mma16816(acc[1][3], af[1], b23[2], b23[3]);
                    mma16816(acc[0][4], af[0], b4[0], b4[1]);
                    mma16816(acc[1][4], af[1], b4[0], b4[1]);
                }
            }
            __syncthreads();  // all warps done reading A

            // Kick next tile's A memcpy BEFORE epilogue -> overlap.
            int nxt = tile + GX_;
            if (nxt < ntiles) fillA(xin, nxt);

            // Epilogue.
#pragma unroll
            for (int mf = 0; mf < 2; mf++) {
#pragma unroll
                for (int half = 0; half < 2; half++) {
                    int rr = wm * 32 + mf * 16 + grp + half * 8;
                    int r = r0 + rr;
                    float hl2[2] = {hl_pre[mf][half].x, hl_pre[mf][half].y};
                    float hr2[2] = {hr_pre[mf][half].x, hr_pre[mf][half].y};
                    float ov[2];
#pragma unroll
                    for (int j = 0; j < 2; j++) {
                        int e = half * 2 + j;
                        float si = acc[mf][0][e] + bias_s[0 * 32 + cl + j];
                        float sl = acc[mf][1][e] + bias_s[1 * 32 + cl + j];
                        float sr = acc[mf][2][e] + bias_s[2 * 32 + cl + j];
                        float so = acc[mf][3][e] + bias_s[3 * 32 + cl + j];
                        float sg = acc[mf][4][e] + bias_s[4 * 32 + cl + j];
                        float cc = sig_fast(si) * tanh_f(sg) + sig_fast(sl) * hl2[j] +
                                   sig_fast(sr) * hr2[j];
                        ov[j] = sig_fast(so) * tanh_f(cc);
                    }
                    *(float2*)&hout[(long long)r * 128 + hcol] = make_float2(ov[0], ov[1]);
                    if (lev < 11) {
                        float p0 = __shfl_down_sync(0xffffffffu, ov[0], 4);
                        float p1 = __shfl_down_sync(0xffffffffu, ov[1], 4);
                        if (grp_even)
                            write_x(xout, (long long)(r >> 1), hcol, ov[0] + p0, ov[1] + p1);
                    }
                }
            }
        }

        if (lev < 11) grid_bar(t, (unsigned)(GCTAS_ * (lev + 1)));
    }
}

// ---------------- launcher ----------------
extern "C" void kernel_launch(void* const* d_in, const int* in_sizes, int n_in,
                              void* d_out, int out_size) {
    const int* ids = (const int*)d_in[0];
    const float* emb = (const float*)d_in[1];
    const float* Wwh = (const float*)d_in[2];
    const float* Whh = (const float*)d_in[3];
    const float* bhh = (const float*)d_in[4];
    float* out = (float*)d_out;

    cudaFuncSetAttribute(fused_all, cudaFuncAttributeMaxDynamicSharedMemorySize, QB_SM);

    prep_both<<<(128 * 640 + 128 * 128 + 255) / 256, 256>>>(Whh, Wwh);
    fused_all<<<dim3(GX_, 4), 256, QB_SM>>>(ids, emb, out, bhh);
}

// round 17
// speedup vs baseline: 1.3265x; 1.2346x over previous
#include <cuda_runtime.h>
#include <cuda_bf16.h>
#include <cuda_fp16.h>

#define BB_ 64
#define LL_ 2048
#define GX_ 74
#define GCTAS_ (GX_ * 4)

typedef unsigned long long ull;
typedef unsigned int u32;

// h ping-pong buffers (f32) for epilogue hl/hr reads.
__device__ float g_bufA[BB_ * LL_ * 128];        // 67 MB
__device__ float g_bufB[BB_ * (LL_ / 2) * 128];  // 33.5 MB
// x buffers in SMEM-IMAGE layout, SINGLE fp16 plane: per 64-row tile
// 4096 u32 (= 64 rows x 64 u32), swizzled exactly like A smem.
__device__ u32 g_xO[BB_ * (LL_ / 2) * 64];       // odd-level inputs  (16.7 MB)
__device__ u32 g_xE[BB_ * (LL_ / 4) * 64];       // even-level inputs (8.4 MB)
// Permuted split W_hh (fp16 hi/lo): [chunk(4)][n(160)][k(128)]
__device__ __align__(16) __half g_Whi[4 * 160 * 128];
__device__ __align__(16) __half g_Wlo[4 * 160 * 128];
// Split W_wh transposed (bf16, embed unchanged): [n(128)][k(128)]
__device__ __align__(16) __nv_bfloat16 g_Ehi[128 * 128];
__device__ __align__(16) __nv_bfloat16 g_Elo[128 * 128];
// Device-wide barrier counter (reset by prep_both every replay).
__device__ unsigned g_bar;

extern __shared__ float smem[];

// ---------------- scalar helpers ----------------
__device__ __forceinline__ float tanhfast(float x) {
    float y; asm("tanh.approx.f32 %0, %1;" : "=f"(y) : "f"(x)); return y;
}
__device__ __forceinline__ float sig_fast(float x) {
    return fmaf(0.5f, tanhfast(0.5f * x), 0.5f);
}
__device__ __forceinline__ float tanh_f(float x) {
    return 1.0f - 2.0f / (__expf(2.0f * x) + 1.0f);
}

// Write x pair (cols col, col+1 of row2) as packed fp16 into plane buffer.
// u32 index mirrors the A-smem swizzle: rr*64 + (2*c4 ^ ((rr&7)<<2)) + j.
__device__ __forceinline__ void write_x(u32* xout, long long row2, int col,
                                        float x0, float x1) {
    int tl = (int)(row2 >> 6);
    int rr = (int)(row2 & 63);
    int c4 = col >> 2, j = (col >> 1) & 1;
    u32 idx = (u32)(rr * 64 + ((2 * c4) ^ ((rr & 7) << 2)) + j);
    __half2 h2 = __floats2half2_rn(x0, x1);
    xout[(long long)tl * 4096 + idx] = *(u32*)&h2;
}

// ---------------- cp.async ----------------
__device__ __forceinline__ void cp16(void* s, const void* g) {
    unsigned a = (unsigned)__cvta_generic_to_shared(s);
    asm volatile("cp.async.cg.shared.global [%0], [%1], 16;" :: "r"(a), "l"(g));
}
#define CP_COMMIT() asm volatile("cp.async.commit_group;")
#define CP_WAIT0()  asm volatile("cp.async.wait_group 0;")

// ---------------- mma.sync helpers ----------------
__device__ __forceinline__ u32 smem_u32(const void* p) {
    u32 a;
    asm("{ .reg .u64 t; cvta.to.shared.u64 t, %1; cvt.u32.u64 %0, t; }" : "=r"(a) : "l"(p));
    return a;
}
__device__ __forceinline__ void ldsm4(u32* r, u32 saddr) {
    asm volatile("ldmatrix.sync.aligned.m8n8.x4.shared.b16 {%0,%1,%2,%3}, [%4];"
                 : "=r"(r[0]), "=r"(r[1]), "=r"(r[2]), "=r"(r[3]) : "r"(saddr));
}
__device__ __forceinline__ void ldsm2(u32* r, u32 saddr) {
    asm volatile("ldmatrix.sync.aligned.m8n8.x2.shared.b16 {%0,%1}, [%2];"
                 : "=r"(r[0]), "=r"(r[1]) : "r"(saddr));
}
// bf16 MMA (embed)
__device__ __forceinline__ void mma16816(float* d, const u32* a, u32 b0, u32 b1) {
    asm volatile(
        "mma.sync.aligned.m16n8k16.row.col.f32.bf16.bf16.f32 "
        "{%0,%1,%2,%3}, {%4,%5,%6,%7}, {%8,%9}, {%0,%1,%2,%3};"
        : "+f"(d[0]), "+f"(d[1]), "+f"(d[2]), "+f"(d[3])
        : "r"(a[0]), "r"(a[1]), "r"(a[2]), "r"(a[3]), "r"(b0), "r"(b1));
}
// fp16 MMA (tree)
__device__ __forceinline__ void mma16816h(float* d, const u32* a, u32 b0, u32 b1) {
    asm volatile(
        "mma.sync.aligned.m16n8k16.row.col.f32.f16.f16.f32 "
        "{%0,%1,%2,%3}, {%4,%5,%6,%7}, {%8,%9}, {%0,%1,%2,%3};"
        : "+f"(d[0]), "+f"(d[1]), "+f"(d[2]), "+f"(d[3])
        : "r"(a[0]), "r"(a[1]), "r"(a[2]), "r"(a[3]), "r"(b0), "r"(b1));
}

// =====================================================================
// Prep: W_hh -> fp16 hi/lo (permuted); W_wh -> bf16 hi/lo; reset barrier.
// =====================================================================
__global__ void prep_both(const float* __restrict__ Whh, const float* __restrict__ Wwh) {
    int idx = blockIdx.x * 256 + threadIdx.x;
    if (idx == 0) g_bar = 0u;
    if (idx < 128 * 640) {
        int k = idx / 640, col = idx - k * 640;
        int g = col >> 7, c = col & 127;
        int chunk = c >> 5, cl = c & 31;
        int n = g * 32 + cl;
        float w = Whh[idx];
        __half hi = __float2half_rn(w);
        __half lo = __float2half_rn(w - __half2float(hi));
        int dst = (chunk * 160 + n) * 128 + k;
        g_Whi[dst] = hi;
        g_Wlo[dst] = lo;
    } else if (idx < 128 * 640 + 128 * 128) {
        int e = idx - 128 * 640;
        int k = e >> 7, n = e & 127;
        float w = Wwh[e];
        __nv_bfloat16 hi = __float2bfloat16_rn(w);
        __nv_bfloat16 lo = __float2bfloat16_rn(w - __bfloat162float(hi));
        g_Ehi[n * 128 + k] = hi;
        g_Elo[n * 128 + k] = lo;
    }
}

// =====================================================================
// MEGA-KERNEL: embed (bf16 3-pass) + 11 tree levels (fp16 2-pass),
// one launch, grid (74,4) = 296 CTAs = 2/SM x 148.
// Tree A-fill = pure cp.async memcpy of the single fp16 x plane,
// issued before the epilogue -> hidden. A ldsm hoisted across W splits.
// smem: A 2x16KB (embed) / 16KB (tree) | B 2x40KB | bias = 115328 B.
// =====================================================================
#define QB_ALO 16384
#define QB_B 32768
#define QB_BIAS 114688
#define QB_SM 115328

__device__ __forceinline__ void grid_bar(int t, unsigned target) {
    __threadfence();
    __syncthreads();
    if (t == 0) {
        atomicAdd(&g_bar, 1u);
        while (atomicAdd(&g_bar, 0u) < target) __nanosleep(64);
    }
    __syncthreads();
    __threadfence();
}

__global__ __launch_bounds__(256, 2) void fused_all(const int* __restrict__ ids,
                                                    const float* __restrict__ emb,
                                                    float* __restrict__ out_param,
                                                    const float* __restrict__ bhh) {
    char* sm = (char*)smem;
    int t = threadIdx.x;
    int chunk = blockIdx.y;
    int bx = blockIdx.x;
    int flat = chunk * GX_ + bx;

    u32 smb = smem_u32(sm);
    int lane = t & 31, warp = t >> 5;
    int wm = warp >> 2, wn = warp & 3;  // 2 x 4
    int t8 = lane >> 3, l7 = lane & 7;
    u32 xsw = (u32)(l7 << 2);
    int arow = wm * 32 + (t8 & 1) * 8 + l7;
    u32 tka = (u32)((t8 >> 1) * 4);
    u32 tkb = (u32)((t8 & 1) * 4);
    int grp = lane >> 2, tid4 = lane & 3;
    int grp_even = !(grp & 1);
    int brow_e = wn * 32 + (t8 >> 1) * 8 + l7;  // embed B mapping
    int rowB = wn * 8 + l7;                     // tree B mapping (gate-aligned)
    int bgsel = t8 >> 1;
    int cl = wn * 8 + tid4 * 2;
    int hcol = chunk * 32 + cl;

    // Pure-memcpy A fill from single-plane fp16 x buffer.
    auto fillA = [&](const u32* xin, int tl) {
        const u32* src = xin + (long long)tl * 4096;
#pragma unroll
        for (int j4 = 0; j4 < 4; j4++) {
            int j = t + j4 * 256;  // 1024 uint4 total
            cp16(sm + j * 16, src + j * 4);
        }
        CP_COMMIT();
    };

    // ================= PHASE 0: embed (bf16 3-pass, unchanged) ==========
    for (int j = t; j < 2 * 128 * 16; j += 256) {
        int split = j >> 11, rem = j & 2047;
        int row = rem >> 4, q = rem & 15;
        const __nv_bfloat16* src = split ? g_Elo : g_Ehi;
        u32 kpb = (u32)(4 * q) ^ ((row & 7) << 2);
        cp16(sm + QB_B + split * 32768 + (row * 64 + kpb) * 4, &src[row * 128 + q * 8]);
    }
    CP_COMMIT();

    for (int tile = flat; tile < 2048; tile += GCTAS_) {
        int r0 = tile * 64;
        __syncthreads();

        for (int i = t; i < 64 * 32; i += 256) {
            int rr = i >> 5, c4 = i & 31;
            int id = ids[r0 + rr];
            float4 v = ((const float4*)emb)[(long long)id * 32 + c4];
            float xv[4] = {v.x, v.y, v.z, v.w};
            __nv_bfloat16 hi[4], lo[4];
#pragma unroll
            for (int j = 0; j < 4; j++) {
                hi[j] = __float2bfloat16_rn(xv[j]);
                lo[j] = __float2bfloat16_rn(xv[j] - __bfloat162float(hi[j]));
            }
            u32 sw = (u32)(2 * c4) ^ ((rr & 7) << 2);
            *(uint2*)(sm + (rr * 64 + sw) * 4) = *(uint2*)hi;
            *(uint2*)(sm + QB_ALO + (rr * 64 + sw) * 4) = *(uint2*)lo;
        }
        CP_WAIT0();
        __syncthreads();

        float acc[2][4][4];
#pragma unroll
        for (int a = 0; a < 2; a++)
#pragma unroll
            for (int b = 0; b < 4; b++)
#pragma unroll
                for (int c = 0; c < 4; c++) acc[a][b][c] = 0.0f;

#pragma unroll 1
        for (int ks = 0; ks < 8; ks++) {
#pragma unroll
            for (int split = 0; split < 3; split++) {
                u32 abase = smb + ((split == 2) ? (u32)QB_ALO : 0u);
                u32 bbase = smb + (u32)QB_B + ((split == 1) ? 32768u : 0u);
                u32 ka = (((u32)(ks * 8) + tka) ^ xsw) * 4;
                u32 kb = (((u32)(ks * 8) + tkb) ^ xsw) * 4;
                u32 af[2][4];
                ldsm4(af[0], abase + (u32)arow * 256 + ka);
                ldsm4(af[1], abase + (u32)(arow + 16) * 256 + ka);
#pragma unroll
                for (int np = 0; np < 2; np++) {
                    u32 bf[4];
                    ldsm4(bf, bbase + (u32)(brow_e + np * 16) * 256 + kb);
                    mma16816(acc[0][2 * np], af[0], bf[0], bf[1]);
                    mma16816(acc[0][2 * np + 1], af[0], bf[2], bf[3]);
                    mma16816(acc[1][2 * np], af[1], bf[0], bf[1]);
                    mma16816(acc[1][2 * np + 1], af[1], bf[2], bf[3]);
                }
            }
        }

        // Epilogue: h0 (f32) + fp16 x_1 plane.
#pragma unroll
        for (int mf = 0; mf < 2; mf++)
#pragma unroll
            for (int nf = 0; nf < 4; nf++) {
                int row = r0 + wm * 32 + mf * 16 + grp;
                int col = wn * 32 + nf * 8 + tid4 * 2;
                *(float2*)&g_bufA[(long long)row * 128 + col] =
                    make_float2(acc[mf][nf][0], acc[mf][nf][1]);
                *(float2*)&g_bufA[(long long)(row + 8) * 128 + col] =
                    make_float2(acc[mf][nf][2], acc[mf][nf][3]);
                float p0 = __shfl_down_sync(0xffffffffu, acc[mf][nf][0], 4);
                float p1 = __shfl_down_sync(0xffffffffu, acc[mf][nf][1], 4);
                float p2 = __shfl_down_sync(0xffffffffu, acc[mf][nf][2], 4);
                float p3 = __shfl_down_sync(0xffffffffu, acc[mf][nf][3], 4);
                if (grp_even) {
                    write_x(g_xO, (long long)(row >> 1), col,
                            acc[mf][nf][0] + p0, acc[mf][nf][1] + p1);
                    write_x(g_xO, (long long)((row + 8) >> 1), col,
                            acc[mf][nf][2] + p2, acc[mf][nf][3] + p3);
                }
            }
    }

    grid_bar(t, (unsigned)GCTAS_);

    // ================= PHASE 1..11: tree (fp16 2-pass) =================
    for (int j = t; j < 2 * 160 * 16; j += 256) {
        int split = j / 2560, rem = j - split * 2560;
        int row = rem >> 4, q = rem & 15;
        const __half* src = split ? g_Wlo : g_Whi;
        u32 kpb = (u32)(4 * q) ^ ((row & 7) << 2);
        cp16(sm + QB_B + split * 40960 + (row * 64 + kpb) * 4,
             &src[(chunk * 160 + row) * 128 + q * 8]);
    }
    CP_COMMIT();
    float* bias_s = (float*)(sm + QB_BIAS);
    for (int j = t; j < 160; j += 256)
        bias_s[j] = 2.0f * bhh[(j >> 5) * 128 + chunk * 32 + (j & 31)];
    CP_WAIT0();
    __syncthreads();

    for (int lev = 1; lev <= 11; lev++) {
        int lg_nhalf = 11 - lev;
        int n_half = 1 << lg_nhalf;
        int ntiles = 2048 >> lev;
        const float* hin = (lev & 1) ? g_bufA : g_bufB;
        float* hout = (lev == 11) ? out_param : ((lev & 1) ? g_bufB : g_bufA);
        const u32* xin = (lev & 1) ? g_xO : g_xE;
        u32* xout = (lev & 1) ? g_xE : g_xO;

        int tile = bx;
        if (tile < ntiles) fillA(xin, tile);  // prologue fill

        for (; tile < ntiles; tile += GX_) {
            int r0 = tile * 64;

            // Prefetch epilogue operands (hl/hr f32) — overlaps cp wait.
            float2 hl_pre[2][2], hr_pre[2][2];
#pragma unroll
            for (int mf = 0; mf < 2; mf++)
#pragma unroll
                for (int half = 0; half < 2; half++) {
                    int rr = wm * 32 + mf * 16 + grp + half * 8;
                    int r = r0 + rr;
                    int b = r >> lg_nhalf;
                    int iw = r - (b << lg_nhalf);
                    long long rowL = (long long)b * (2 * n_half) + 2 * iw;
                    hl_pre[mf][half] = *(const float2*)&hin[rowL * 128 + hcol];
                    hr_pre[mf][half] = *(const float2*)&hin[(rowL + 1) * 128 + hcol];
                }

            CP_WAIT0();     // A plane landed
            __syncthreads();

            float acc[2][5][4];
#pragma unroll
            for (int a = 0; a < 2; a++)
#pragma unroll
                for (int g = 0; g < 5; g++)
#pragma unroll
                    for (int c = 0; c < 4; c++) acc[a][g][c] = 0.0f;

#pragma unroll 1
            for (int ks = 0; ks < 8; ks++) {
                u32 ka = (((u32)(ks * 8) + tka) ^ xsw) * 4;
                u32 kb = (((u32)(ks * 8) + tkb) ^ xsw) * 4;
                u32 af[2][4];
                ldsm4(af[0], smb + (u32)arow * 256 + ka);
                ldsm4(af[1], smb + (u32)(arow + 16) * 256 + ka);
#pragma unroll
                for (int split = 0; split < 2; split++) {
                    u32 bbase = smb + QB_B + (split ? 40960u : 0u);
                    u32 b01[4], b23[4], b4[2];
                    ldsm4(b01, bbase + (u32)((0 + bgsel) * 32 + rowB) * 256 + kb);
                    ldsm4(b23, bbase + (u32)((2 + bgsel) * 32 + rowB) * 256 + kb);
                    ldsm2(b4, bbase + (u32)(4 * 32 + rowB) * 256 + kb);
                    mma16816h(acc[0][0], af[0], b01[0], b01[1]);
                    mma16816h(acc[1][0], af[1], b01[0], b01[1]);
                    mma16816h(acc[0][1], af[0], b01[2], b01[3]);
                    mma16816h(acc[1][1], af[1], b01[2], b01[3]);
                    mma16816h(acc[0][2], af[0], b23[0], b23[1]);
                    mma16816h(acc[1][2], af[1], b23[0], b23[1]);
                    mma16816h(acc[0][3], af[0], b23[2], b23[3]);
                    mma16816h(acc[1][3], af[1], b23[2], b23[3]);
                    mma16816h(acc[0][4], af[0], b4[0], b4[1]);
                    mma16816h(acc[1][4], af[1], b4[0], b4[1]);
                }
            }
            __syncthreads();  // all warps done reading A

            // Kick next tile's A memcpy BEFORE epilogue -> overlap.
            int nxt = tile + GX_;
            if (nxt < ntiles) fillA(xin, nxt);

            // Epilogue.
#pragma unroll
            for (int mf = 0; mf < 2; mf++) {
#pragma unroll
                for (int half = 0; half < 2; half++) {
                    int rr = wm * 32 + mf * 16 + grp + half * 8;
                    int r = r0 + rr;
                    float hl2[2] = {hl_pre[mf][half].x, hl_pre[mf][half].y};
                    float hr2[2] = {hr_pre[mf][half].x, hr_pre[mf][half].y};
                    float ov[2];
#pragma unroll
                    for (int j = 0; j < 2; j++) {
                        int e = half * 2 + j;
                        float si = acc[mf][0][e] + bias_s[0 * 32 + cl + j];
                        float sl = acc[mf][1][e] + bias_s[1 * 32 + cl + j];
                        float sr = acc[mf][2][e] + bias_s[2 * 32 + cl + j];
                        float so = acc[mf][3][e] + bias_s[3 * 32 + cl + j];
                        float sg = acc[mf][4][e] + bias_s[4 * 32 + cl + j];
                        float cc = sig_fast(si) * tanh_f(sg) + sig_fast(sl) * hl2[j] +
                                   sig_fast(sr) * hr2[j];
                        ov[j] = sig_fast(so) * tanh_f(cc);
                    }
                    *(float2*)&hout[(long long)r * 128 + hcol] = make_float2(ov[0], ov[1]);
                    if (lev < 11) {
                        float p0 = __shfl_down_sync(0xffffffffu, ov[0], 4);
                        float p1 = __shfl_down_sync(0xffffffffu, ov[1], 4);
                        if (grp_even)
                            write_x(xout, (long long)(r >> 1), hcol, ov[0] + p0, ov[1] + p1);
                    }
                }
            }
        }

        if (lev < 11) grid_bar(t, (unsigned)(GCTAS_ * (lev + 1)));
    }
}

// ---------------- launcher ----------------
extern "C" void kernel_launch(void* const* d_in, const int* in_sizes, int n_in,
                              void* d_out, int out_size) {
    const int* ids = (const int*)d_in[0];
    const float* emb = (const float*)d_in[1];
    const float* Wwh = (const float*)d_in[2];
    const float* Whh = (const float*)d_in[3];
    const float* bhh = (const float*)d_in[4];
    float* out = (float*)d_out;

    cudaFuncSetAttribute(fused_all, cudaFuncAttributeMaxDynamicSharedMemorySize, QB_SM);

    prep_both<<<(128 * 640 + 128 * 128 + 255) / 256, 256>>>(Whh, Wwh);
    fused_all<<<dim3(GX_, 4), 256, QB_SM>>>(ids, emb, out, bhh);
}